// round 2
// baseline (speedup 1.0000x reference)
#include <cuda_runtime.h>
#include <math.h>

#define NB 2
#define NT 1024
#define NC 1024
#define NH 16
#define NNh 64
#define NBT (NB*NT)

// ---------------- scratch (device globals; no allocation allowed) ----------------
__device__ float g_xxx[NBT*NC];
__device__ float g_mixh[NBT*128];
__device__ float g_xrg[NBT*NC];
__device__ float g_xwa[NBT*NC];
__device__ float g_xk [NBT*NC];
__device__ float g_xv [NBT*NC];
__device__ float g_r  [NBT*NC];
__device__ float g_k  [NBT*NC];
__device__ float g_v  [NBT*NC];
__device__ float g_w1t[NBT*64];
__device__ float g_a1 [NBT*16];
__device__ float g_ma1[NBT*16];
__device__ float g_kk1[NBT*16];
__device__ float g_mk1[NBT*16];
__device__ float g_g1 [NBT*128];
__device__ float g_g  [NBT*NC];
__device__ float g_ew [NBT*NC];
__device__ float g_kf [NBT*NC];
__device__ float g_kkn[NBT*NC];
__device__ float g_bb [NBT*NC];
__device__ float g_y  [NBT*NC];
__device__ float g_z  [NBT*NC];

// ---------------- packed f32x2 helpers ----------------
__device__ __forceinline__ unsigned long long pk2(float lo, float hi) {
    unsigned long long r;
    asm("mov.b64 %0, {%1, %2};" : "=l"(r) : "f"(lo), "f"(hi));
    return r;
}
__device__ __forceinline__ void fma2(unsigned long long& d, unsigned long long a, unsigned long long b) {
    asm("fma.rn.f32x2 %0, %1, %2, %0;" : "+l"(d) : "l"(a), "l"(b));
}

// ---------------- generic C = A(MxK) @ W(NxK)^T , optional tanh epilogue ----------------
__global__ __launch_bounds__(256) void gemm_tn_kernel(
    const float* __restrict__ A, const float* __restrict__ W, float* __restrict__ C,
    int M, int N, int K, int act)
{
    __shared__ __align__(16) float As[16][128];
    __shared__ __align__(16) float Bs[16][128];
    const int bm = blockIdx.y * 128;
    const int bn = blockIdx.x * 128;
    const int tid = threadIdx.x;
    const int tx = tid & 15, ty = tid >> 4;
    const int lr = tid >> 2;
    const int lk = (tid & 3) << 2;
    unsigned long long acc[8][4];
    #pragma unroll
    for (int i = 0; i < 8; i++)
        #pragma unroll
        for (int j = 0; j < 4; j++) acc[i][j] = 0ull;

    for (int k0 = 0; k0 < K; k0 += 16) {
        #pragma unroll
        for (int rr = 0; rr < 2; rr++) {
            int row = lr + rr*64;
            float4 av = *(const float4*)(A + (size_t)(bm+row)*K + k0 + lk);
            As[lk+0][row]=av.x; As[lk+1][row]=av.y; As[lk+2][row]=av.z; As[lk+3][row]=av.w;
            int wrow = bn + row;
            float4 bv = make_float4(0.f,0.f,0.f,0.f);
            if (wrow < N) bv = *(const float4*)(W + (size_t)wrow*K + k0 + lk);
            Bs[lk+0][row]=bv.x; Bs[lk+1][row]=bv.y; Bs[lk+2][row]=bv.z; Bs[lk+3][row]=bv.w;
        }
        __syncthreads();
        #pragma unroll
        for (int kk = 0; kk < 16; kk++) {
            float4 a0 = *(const float4*)&As[kk][ty*8];
            float4 a1 = *(const float4*)&As[kk][ty*8+4];
            ulonglong2 q0 = *(const ulonglong2*)&Bs[kk][tx*8];
            ulonglong2 q1 = *(const ulonglong2*)&Bs[kk][tx*8+4];
            unsigned long long bv0=q0.x, bv1=q0.y, bv2=q1.x, bv3=q1.y;
            float a8[8] = {a0.x,a0.y,a0.z,a0.w,a1.x,a1.y,a1.z,a1.w};
            #pragma unroll
            for (int i = 0; i < 8; i++) {
                unsigned long long ad = pk2(a8[i], a8[i]);
                fma2(acc[i][0], ad, bv0);
                fma2(acc[i][1], ad, bv1);
                fma2(acc[i][2], ad, bv2);
                fma2(acc[i][3], ad, bv3);
            }
        }
        __syncthreads();
    }
    #pragma unroll
    for (int i = 0; i < 8; i++) {
        int m = bm + ty*8 + i;
        #pragma unroll
        for (int j = 0; j < 4; j++) {
            float2 f = *(float2*)&acc[i][j];
            if (act == 1) { f.x = tanhf(f.x); f.y = tanhf(f.y); }
            int n0 = bn + tx*8 + 2*j;
            if (n0     < N) C[(size_t)m*N + n0]     = f.x;
            if (n0 + 1 < N) C[(size_t)m*N + n0 + 1] = f.y;
        }
    }
}

// ---------------- token shift: xxx = x + (xprev - x) * time_maa_x ----------------
__global__ __launch_bounds__(256) void shift_kernel(const float* __restrict__ x,
                                                    const float* __restrict__ tmx)
{
    const size_t i = (size_t)blockIdx.x*256 + threadIdx.x;
    const int c = (int)(i & (NC-1));
    const size_t tok = i >> 10;
    const int tt = (int)(tok & (NT-1));
    float xv = x[i];
    float xp = (tt == 0) ? 0.f : x[i - NC];
    g_xxx[i] = fmaf(xp - xv, tmx[c], xv);
}

// ---------------- 4-way LoRA mix apply: xrg/xwa/xk/xv ----------------
__global__ __launch_bounds__(256) void mix_apply_kernel(
    const float* __restrict__ x, const float* __restrict__ tm,
    const float* __restrict__ w2)
{
    const int tok = blockIdx.x;
    const int tid = threadIdx.x;
    __shared__ float mh[128];
    if (tid < 128) mh[tid] = g_mixh[tok*128 + tid];
    __syncthreads();
    const int tt = tok & (NT-1);
    const float* xr = x + (size_t)tok*NC;
    #pragma unroll
    for (int it = 0; it < 4; it++) {
        const int c = tid + it*256;
        float xv = xr[c];
        float xp = (tt == 0) ? 0.f : xr[c - NC];
        float xx = xp - xv;
        float d0=0.f, d1=0.f, d2=0.f, d3=0.f;
        const float* w0 = w2 + (size_t)0*NC*32 + (size_t)c*32;
        const float* w1 = w2 + (size_t)1*NC*32 + (size_t)c*32;
        const float* wq = w2 + (size_t)2*NC*32 + (size_t)c*32;
        const float* w3 = w2 + (size_t)3*NC*32 + (size_t)c*32;
        #pragma unroll
        for (int d = 0; d < 32; d++) {
            d0 = fmaf(mh[d],      w0[d], d0);
            d1 = fmaf(mh[32+d],   w1[d], d1);
            d2 = fmaf(mh[64+d],   wq[d], d2);
            d3 = fmaf(mh[96+d],   w3[d], d3);
        }
        const size_t o = (size_t)tok*NC + c;
        g_xrg[o] = fmaf(xx, tm[c]        + d0, xv);
        g_xwa[o] = fmaf(xx, tm[NC+c]     + d1, xv);
        g_xk [o] = fmaf(xx, tm[2*NC+c]   + d2, xv);
        g_xv [o] = fmaf(xx, tm[3*NC+c]   + d3, xv);
    }
}

// ---------------- post: decay/exp, a/ma/mk sigmoids, kk normalize, k final, b ----------------
__global__ __launch_bounds__(256) void post_kernel(
    const float* __restrict__ td,  const float* __restrict__ tdw2,
    const float* __restrict__ ta5, const float* __restrict__ taw2,
    const float* __restrict__ tkw2,
    const float* __restrict__ tma_, const float* __restrict__ maw2,
    const float* __restrict__ tmk_, const float* __restrict__ mkw2)
{
    const int tok = blockIdx.x;
    const int tid = threadIdx.x;
    __shared__ float sw1[64], sa1[16], sma1[16], skk1[16], smk1[16];
    if (tid < 64)       sw1[tid]       = g_w1t[tok*64 + tid];
    else if (tid < 80)  sa1[tid-64]    = g_a1 [tok*16 + (tid-64)];
    else if (tid < 96)  sma1[tid-80]   = g_ma1[tok*16 + (tid-80)];
    else if (tid < 112) skk1[tid-96]   = g_kk1[tok*16 + (tid-96)];
    else if (tid < 128) smk1[tid-112]  = g_mk1[tok*16 + (tid-112)];
    __syncthreads();
    const size_t base = (size_t)tok*NC;
    float kkv[4], avv[4], ewv[4], kfv[4];
    float ss = 0.f;
    #pragma unroll
    for (int q = 0; q < 4; q++) {
        const int c = tid*4 + q;
        const float kraw = g_k[base + c];
        float u = td[c];
        const float* w2r = tdw2 + (size_t)c*64;
        #pragma unroll
        for (int d = 0; d < 64; d++) u = fmaf(sw1[d], w2r[d], u);
        float spz = -u;
        float sp = (spz > 15.f) ? spz : log1pf(expf(spz));
        float w = -sp - 0.5f;
        ewv[q] = expf(w);
        float ua  = ta5[c];  const float* ar  = taw2 + (size_t)c*16;
        float uma = tma_[c]; const float* mar = maw2 + (size_t)c*16;
        float umk = tmk_[c]; const float* mkr = mkw2 + (size_t)c*16;
        float uk  = 0.f;     const float* kr  = tkw2 + (size_t)c*16;
        #pragma unroll
        for (int d = 0; d < 16; d++) {
            ua  = fmaf(sa1[d],  ar[d],  ua);
            uma = fmaf(sma1[d], mar[d], uma);
            umk = fmaf(smk1[d], mkr[d], umk);
            uk  = fmaf(skk1[d], kr[d],  uk);
        }
        float a  = 1.f/(1.f + expf(-ua));
        float ma = 1.f/(1.f + expf(-uma));
        float mk = 1.f/(1.f + expf(-umk));
        avv[q] = a;
        float kq = kraw + uk;
        kkv[q] = kq;
        ss = fmaf(kq, kq, ss);
        kfv[q] = kraw * (ma + a*(1.f - ma)) * expf(w*mk);
    }
    ss += __shfl_xor_sync(0xffffffffu, ss, 1);
    ss += __shfl_xor_sync(0xffffffffu, ss, 2);
    ss += __shfl_xor_sync(0xffffffffu, ss, 4);
    ss += __shfl_xor_sync(0xffffffffu, ss, 8);
    const float rinv = 1.f / fmaxf(sqrtf(ss), 1e-12f);
    #pragma unroll
    for (int q = 0; q < 4; q++) {
        const int c = tid*4 + q;
        float kkn = kkv[q]*rinv;
        g_kkn[base+c] = kkn;
        g_bb [base+c] = -kkn*avv[q];
        g_ew [base+c] = ewv[q];
        g_kf [base+c] = kfv[q];
    }
}

// ---------------- RWKV-7 scan: one block per (b,h), 128 threads (2 per state row) ----------------
__global__ __launch_bounds__(128) void scan_kernel()
{
    const int bh = blockIdx.x;
    const int b  = bh >> 4;
    const int h  = bh & 15;
    const int tid  = threadIdx.x;
    const int row  = tid >> 1;
    const int half = tid & 1;
    const int off  = half * 32;
    __shared__ __align__(16) float sr[64], se[64], sk[64], sv[64], sq[64], sb[64];
    float S[32];
    #pragma unroll
    for (int j = 0; j < 32; j++) S[j] = 0.f;
    const size_t base = ((size_t)b*NT)*NC + h*NNh;
    float pr=0.f, pe=0.f, pk=0.f, pv=0.f, pq=0.f, pb=0.f;
    if (tid < 64) {
        pr = g_r [base+tid]; pe = g_ew [base+tid]; pk = g_kf[base+tid];
        pv = g_v [base+tid]; pq = g_kkn[base+tid]; pb = g_bb[base+tid];
    }
    for (int t = 0; t < NT; t++) {
        if (tid < 64) { sr[tid]=pr; se[tid]=pe; sk[tid]=pk; sv[tid]=pv; sq[tid]=pq; sb[tid]=pb; }
        __syncthreads();
        if (t + 1 < NT && tid < 64) {
            const size_t nb = base + (size_t)(t+1)*NC;
            pr = g_r [nb+tid]; pe = g_ew [nb+tid]; pk = g_kf[nb+tid];
            pv = g_v [nb+tid]; pq = g_kkn[nb+tid]; pb = g_bb[nb+tid];
        }
        const float4* q4 = (const float4*)(sq + off);
        float s0=0.f, s1=0.f, s2=0.f, s3=0.f;
        #pragma unroll
        for (int j = 0; j < 8; j++) {
            float4 q = q4[j];
            s0 = fmaf(S[4*j+0], q.x, s0);
            s1 = fmaf(S[4*j+1], q.y, s1);
            s2 = fmaf(S[4*j+2], q.z, s2);
            s3 = fmaf(S[4*j+3], q.w, s3);
        }
        float sab = (s0+s1)+(s2+s3);
        sab += __shfl_xor_sync(0xffffffffu, sab, 1);
        const float vv = sv[row];
        const float4* e4 = (const float4*)(se + off);
        const float4* b4 = (const float4*)(sb + off);
        const float4* k4 = (const float4*)(sk + off);
        const float4* r4 = (const float4*)(sr + off);
        float y0=0.f, y1=0.f, y2=0.f, y3=0.f;
        #pragma unroll
        for (int j = 0; j < 8; j++) {
            float4 e = e4[j], bv = b4[j], kv = k4[j], rv = r4[j];
            float t0 = fmaf(vv, kv.x, fmaf(sab, bv.x, S[4*j+0]*e.x));
            float t1 = fmaf(vv, kv.y, fmaf(sab, bv.y, S[4*j+1]*e.y));
            float t2 = fmaf(vv, kv.z, fmaf(sab, bv.z, S[4*j+2]*e.z));
            float t3 = fmaf(vv, kv.w, fmaf(sab, bv.w, S[4*j+3]*e.w));
            S[4*j+0]=t0; S[4*j+1]=t1; S[4*j+2]=t2; S[4*j+3]=t3;
            y0 = fmaf(t0, rv.x, y0);
            y1 = fmaf(t1, rv.y, y1);
            y2 = fmaf(t2, rv.z, y2);
            y3 = fmaf(t3, rv.w, y3);
        }
        float yv = (y0+y1)+(y2+y3);
        yv += __shfl_xor_sync(0xffffffffu, yv, 1);
        if (half == 0) g_y[base + (size_t)t*NC + row] = yv;
        __syncthreads();
    }
}

// ---------------- tail: GroupNorm + r.k bonus + gate ----------------
__global__ __launch_bounds__(256) void tail_kernel(
    const float* __restrict__ lnw, const float* __restrict__ lnb,
    const float* __restrict__ faaaa)
{
    const int tok = blockIdx.x;
    const int tid = threadIdx.x;
    const size_t base = (size_t)tok*NC;
    float yv[4], vv[4];
    float sy=0.f, syy=0.f, srk=0.f;
    #pragma unroll
    for (int q = 0; q < 4; q++) {
        const int c = tid*4 + q;
        float y = g_y[base+c];
        float r = g_r[base+c];
        float k = g_kf[base+c];
        vv[q] = g_v[base+c];
        yv[q] = y;
        sy += y;
        syy = fmaf(y, y, syy);
        srk = fmaf(r*k, faaaa[c], srk);
    }
    #pragma unroll
    for (int o = 1; o < 16; o <<= 1) {
        sy  += __shfl_xor_sync(0xffffffffu, sy,  o);
        syy += __shfl_xor_sync(0xffffffffu, syy, o);
        srk += __shfl_xor_sync(0xffffffffu, srk, o);
    }
    const float mu  = sy * (1.f/64.f);
    const float var = syy * (1.f/64.f) - mu*mu;
    const float inv = 1.f / sqrtf(var + 0.00064f);
    #pragma unroll
    for (int q = 0; q < 4; q++) {
        const int c = tid*4 + q;
        float yn = (yv[q] - mu) * inv * lnw[c] + lnb[c];
        g_z[base+c] = (yn + srk*vv[q]) * g_g[base+c];
    }
}

// ---------------- host ----------------
static inline void launch_gemm(const float* A, const float* W, float* C,
                               int M, int N, int K, int act)
{
    dim3 grid((N + 127)/128, M/128);
    gemm_tn_kernel<<<grid, 256>>>(A, W, C, M, N, K, act);
}

extern "C" void kernel_launch(void* const* d_in, const int* in_sizes, int n_in,
                              void* d_out, int out_size)
{
    const float* x     = (const float*)d_in[0];
    const float* tmx   = (const float*)d_in[1];
    const float* tm    = (const float*)d_in[2];
    const float* maaw1 = (const float*)d_in[3];
    const float* maaw2 = (const float*)d_in[4];
    const float* td    = (const float*)d_in[5];
    const float* tdw1  = (const float*)d_in[6];
    const float* tdw2  = (const float*)d_in[7];
    const float* ta5   = (const float*)d_in[8];
    const float* taw1  = (const float*)d_in[9];
    const float* taw2  = (const float*)d_in[10];
    const float* tkw1  = (const float*)d_in[11];
    const float* tkw2  = (const float*)d_in[12];
    const float* gw1   = (const float*)d_in[13];
    const float* gw2   = (const float*)d_in[14];
    const float* tma_  = (const float*)d_in[15];
    const float* maw1  = (const float*)d_in[16];
    const float* maw2  = (const float*)d_in[17];
    const float* tmk_  = (const float*)d_in[18];
    const float* mkw1  = (const float*)d_in[19];
    const float* mkw2  = (const float*)d_in[20];
    const float* recw  = (const float*)d_in[21];
    const float* keyw  = (const float*)d_in[22];
    const float* valw  = (const float*)d_in[23];
    const float* outw  = (const float*)d_in[24];
    const float* lnw   = (const float*)d_in[25];
    const float* lnb   = (const float*)d_in[26];
    const float* faaaa = (const float*)d_in[27];
    float* out = (float*)d_out;

    float *p_xxx, *p_mixh, *p_xrg, *p_xwa, *p_xk, *p_xv;
    float *p_r, *p_k, *p_v, *p_w1t, *p_a1, *p_ma1, *p_kk1, *p_mk1, *p_g1, *p_g, *p_z;
    cudaGetSymbolAddress((void**)&p_xxx,  g_xxx);
    cudaGetSymbolAddress((void**)&p_mixh, g_mixh);
    cudaGetSymbolAddress((void**)&p_xrg,  g_xrg);
    cudaGetSymbolAddress((void**)&p_xwa,  g_xwa);
    cudaGetSymbolAddress((void**)&p_xk,   g_xk);
    cudaGetSymbolAddress((void**)&p_xv,   g_xv);
    cudaGetSymbolAddress((void**)&p_r,    g_r);
    cudaGetSymbolAddress((void**)&p_k,    g_k);
    cudaGetSymbolAddress((void**)&p_v,    g_v);
    cudaGetSymbolAddress((void**)&p_w1t,  g_w1t);
    cudaGetSymbolAddress((void**)&p_a1,   g_a1);
    cudaGetSymbolAddress((void**)&p_ma1,  g_ma1);
    cudaGetSymbolAddress((void**)&p_kk1,  g_kk1);
    cudaGetSymbolAddress((void**)&p_mk1,  g_mk1);
    cudaGetSymbolAddress((void**)&p_g1,   g_g1);
    cudaGetSymbolAddress((void**)&p_g,    g_g);
    cudaGetSymbolAddress((void**)&p_z,    g_z);

    // 1. token shift
    shift_kernel<<<(NBT*NC)/256, 256>>>(x, tmx);
    // 2. mix hidden = tanh(xxx @ maa_w1^T)   (2048x128, K=1024)
    launch_gemm(p_xxx, maaw1, p_mixh, NBT, 128, NC, 1);
    // 3. apply 4-way mixing -> xrg, xwa, xk, xv
    mix_apply_kernel<<<NBT, 256>>>(x, tm, maaw2);
    // 4. big projections
    launch_gemm(p_xrg, recw, p_r, NBT, NC, NC, 0);
    launch_gemm(p_xk,  keyw, p_k, NBT, NC, NC, 0);
    launch_gemm(p_xv,  valw, p_v, NBT, NC, NC, 0);
    // 5. LoRA hiddens
    launch_gemm(p_xwa, tdw1, p_w1t, NBT, 64,  NC, 1);  // tanh
    launch_gemm(p_xwa, taw1, p_a1,  NBT, 16,  NC, 0);
    launch_gemm(p_xwa, maw1, p_ma1, NBT, 16,  NC, 0);
    launch_gemm(p_xk,  tkw1, p_kk1, NBT, 16,  NC, 1);  // tanh
    launch_gemm(p_xk,  mkw1, p_mk1, NBT, 16,  NC, 0);
    launch_gemm(p_xrg, gw1,  p_g1,  NBT, 128, NC, 1);  // tanh
    // 6. gate g = g1 @ gate_w2^T  (K=128)
    launch_gemm(p_g1, gw2, p_g, NBT, NC, 128, 0);
    // 7. elementwise post: ew, kk_norm, k_final, b
    post_kernel<<<NBT, 256>>>(td, tdw2, ta5, taw2, tkw2, tma_, maw2, tmk_, mkw2);
    // 8. RWKV-7 scan
    scan_kernel<<<NB*NH, 128>>>();
    // 9. GroupNorm + bonus + gate
    tail_kernel<<<NBT, 256>>>(lnw, lnb, faaaa);
    // 10. output projection
    launch_gemm(p_z, outw, out, NBT, NC, NC, 0);

    (void)in_sizes; (void)n_in; (void)out_size; (void)tdw1;
}

// round 3
// speedup vs baseline: 1.1953x; 1.1953x over previous
#include <cuda_runtime.h>
#include <math.h>

#define NB 2
#define NT 1024
#define NC 1024
#define NH 16
#define NNh 64
#define NBT (NB*NT)

// ---------------- scratch (device globals; no allocation allowed) ----------------
__device__ float g_xxx[NBT*NC];
__device__ float g_mixh[NBT*128];
__device__ float g_xrg[NBT*NC];
__device__ float g_xwa[NBT*NC];
__device__ float g_xk [NBT*NC];
__device__ float g_xv [NBT*NC];
__device__ float g_r  [NBT*NC];
__device__ float g_k  [NBT*NC];
__device__ float g_v  [NBT*NC];
__device__ float g_w1t[NBT*64];
__device__ float g_a1 [NBT*16];
__device__ float g_ma1[NBT*16];
__device__ float g_kk1[NBT*16];
__device__ float g_mk1[NBT*16];
__device__ float g_g1 [NBT*128];
__device__ float g_g  [NBT*NC];
__device__ float g_ew [NBT*NC];
__device__ float g_kf [NBT*NC];
__device__ float g_kkn[NBT*NC];
__device__ float g_bb [NBT*NC];
__device__ float g_y  [NBT*NC];
__device__ float g_z  [NBT*NC];

// ---------------- packed f32x2 helpers ----------------
__device__ __forceinline__ unsigned long long pk2(float lo, float hi) {
    unsigned long long r;
    asm("mov.b64 %0, {%1, %2};" : "=l"(r) : "f"(lo), "f"(hi));
    return r;
}
__device__ __forceinline__ void fma2(unsigned long long& d, unsigned long long a, unsigned long long b) {
    asm("fma.rn.f32x2 %0, %1, %2, %0;" : "+l"(d) : "l"(a), "l"(b));
}

// ---------------- BIG GEMM: C = A(MxK) @ W(NxK)^T, 128x64 tile, N%64==0, M%128==0 ----------------
__global__ __launch_bounds__(256, 2) void gemm_big_kernel(
    const float* __restrict__ A, const float* __restrict__ W, float* __restrict__ C,
    int M, int N, int K)
{
    __shared__ __align__(16) float As[16][132];
    __shared__ __align__(16) float Ws[16][68];
    const int bm = blockIdx.y * 128;
    const int bn = blockIdx.x * 64;
    const int tid = threadIdx.x;
    const int tx = tid & 15;   // n-group: 4 cols
    const int ty = tid >> 4;   // m-group: 8 rows
    // A loader: row lr (0..127), k offset (tid&1)*8 (two float4)
    const int lr = tid >> 1;
    const int lka = (tid & 1) * 8;
    // W loader: row wr (0..63), k offset (tid&3)*4
    const int wr = tid >> 2;
    const int wka = (tid & 3) * 4;

    unsigned long long acc[8][2];
    #pragma unroll
    for (int i = 0; i < 8; i++) { acc[i][0] = 0ull; acc[i][1] = 0ull; }

    for (int k0 = 0; k0 < K; k0 += 16) {
        float4 a0 = *(const float4*)(A + (size_t)(bm+lr)*K + k0 + lka);
        float4 a1 = *(const float4*)(A + (size_t)(bm+lr)*K + k0 + lka + 4);
        float4 wv = *(const float4*)(W + (size_t)(bn+wr)*K + k0 + wka);
        As[lka+0][lr]=a0.x; As[lka+1][lr]=a0.y; As[lka+2][lr]=a0.z; As[lka+3][lr]=a0.w;
        As[lka+4][lr]=a1.x; As[lka+5][lr]=a1.y; As[lka+6][lr]=a1.z; As[lka+7][lr]=a1.w;
        Ws[wka+0][wr]=wv.x; Ws[wka+1][wr]=wv.y; Ws[wka+2][wr]=wv.z; Ws[wka+3][wr]=wv.w;
        __syncthreads();
        #pragma unroll
        for (int kk = 0; kk < 16; kk++) {
            float4 f0 = *(const float4*)&As[kk][ty*8];
            float4 f1 = *(const float4*)&As[kk][ty*8+4];
            ulonglong2 q = *(const ulonglong2*)&Ws[kk][tx*4];
            float a8[8] = {f0.x,f0.y,f0.z,f0.w,f1.x,f1.y,f1.z,f1.w};
            #pragma unroll
            for (int i = 0; i < 8; i++) {
                unsigned long long ad = pk2(a8[i], a8[i]);
                fma2(acc[i][0], ad, q.x);
                fma2(acc[i][1], ad, q.y);
            }
        }
        __syncthreads();
    }
    #pragma unroll
    for (int i = 0; i < 8; i++) {
        int m = bm + ty*8 + i;
        float2 f0 = *(float2*)&acc[i][0];
        float2 f1 = *(float2*)&acc[i][1];
        float4 o = make_float4(f0.x, f0.y, f1.x, f1.y);
        *(float4*)(C + (size_t)m*N + bn + tx*4) = o;
    }
}

// ---------------- THIN GEMM: C = A(MxK) @ W(NxK)^T, N<=128, 32x32 tile ----------------
__global__ __launch_bounds__(256) void gemm_thin_kernel(
    const float* __restrict__ A, const float* __restrict__ W, float* __restrict__ C,
    int N, int K, int act)
{
    __shared__ float As[32][33];
    __shared__ __align__(16) float Ws[32][36];
    const int bm = blockIdx.x * 32;
    const int bn = blockIdx.y * 32;
    const int tid = threadIdx.x;
    const int lr = tid >> 3;          // 0..31 (row for loads)
    const int lk = (tid & 7) * 4;     // k offset
    const int ty = tid >> 3;          // compute row 0..31
    const int tx = tid & 7;           // compute n-group (4 cols)

    float acc0=0.f, acc1=0.f, acc2=0.f, acc3=0.f;
    const int wrow = bn + lr;

    for (int k0 = 0; k0 < K; k0 += 32) {
        float4 av = *(const float4*)(A + (size_t)(bm+lr)*K + k0 + lk);
        float4 wv = make_float4(0.f,0.f,0.f,0.f);
        if (wrow < N) wv = *(const float4*)(W + (size_t)wrow*K + k0 + lk);
        As[lk+0][lr]=av.x; As[lk+1][lr]=av.y; As[lk+2][lr]=av.z; As[lk+3][lr]=av.w;
        Ws[lk+0][lr]=wv.x; Ws[lk+1][lr]=wv.y; Ws[lk+2][lr]=wv.z; Ws[lk+3][lr]=wv.w;
        __syncthreads();
        #pragma unroll
        for (int kk = 0; kk < 32; kk++) {
            float a = As[kk][ty];
            float4 w4 = *(const float4*)&Ws[kk][tx*4];
            acc0 = fmaf(a, w4.x, acc0);
            acc1 = fmaf(a, w4.y, acc1);
            acc2 = fmaf(a, w4.z, acc2);
            acc3 = fmaf(a, w4.w, acc3);
        }
        __syncthreads();
    }
    if (act) { acc0=tanhf(acc0); acc1=tanhf(acc1); acc2=tanhf(acc2); acc3=tanhf(acc3); }
    const int m = bm + ty;
    const int n0 = bn + tx*4;
    float* cr = C + (size_t)m*N;
    if (n0   < N) cr[n0]   = acc0;
    if (n0+1 < N) cr[n0+1] = acc1;
    if (n0+2 < N) cr[n0+2] = acc2;
    if (n0+3 < N) cr[n0+3] = acc3;
}

// ---------------- token shift: xxx = x + (xprev - x) * time_maa_x ----------------
__global__ __launch_bounds__(256) void shift_kernel(const float* __restrict__ x,
                                                    const float* __restrict__ tmx)
{
    const size_t i = (size_t)blockIdx.x*256 + threadIdx.x;
    const int c = (int)(i & (NC-1));
    const size_t tok = i >> 10;
    const int tt = (int)(tok & (NT-1));
    float xv = x[i];
    float xp = (tt == 0) ? 0.f : x[i - NC];
    g_xxx[i] = fmaf(xp - xv, tmx[c], xv);
}

// ---------------- 4-way LoRA mix apply: xrg/xwa/xk/xv ----------------
__global__ __launch_bounds__(256) void mix_apply_kernel(
    const float* __restrict__ x, const float* __restrict__ tm,
    const float* __restrict__ w2)
{
    const int tok = blockIdx.x;
    const int tid = threadIdx.x;
    __shared__ float mh[128];
    if (tid < 128) mh[tid] = g_mixh[tok*128 + tid];
    __syncthreads();
    const int tt = tok & (NT-1);
    const float* xr = x + (size_t)tok*NC;
    #pragma unroll
    for (int it = 0; it < 4; it++) {
        const int c = tid + it*256;
        float xv = xr[c];
        float xp = (tt == 0) ? 0.f : xr[c - NC];
        float xx = xp - xv;
        float d0=0.f, d1=0.f, d2=0.f, d3=0.f;
        const float* w0 = w2 + (size_t)0*NC*32 + (size_t)c*32;
        const float* w1 = w2 + (size_t)1*NC*32 + (size_t)c*32;
        const float* wq = w2 + (size_t)2*NC*32 + (size_t)c*32;
        const float* w3 = w2 + (size_t)3*NC*32 + (size_t)c*32;
        #pragma unroll
        for (int d = 0; d < 32; d++) {
            d0 = fmaf(mh[d],      w0[d], d0);
            d1 = fmaf(mh[32+d],   w1[d], d1);
            d2 = fmaf(mh[64+d],   wq[d], d2);
            d3 = fmaf(mh[96+d],   w3[d], d3);
        }
        const size_t o = (size_t)tok*NC + c;
        g_xrg[o] = fmaf(xx, tm[c]        + d0, xv);
        g_xwa[o] = fmaf(xx, tm[NC+c]     + d1, xv);
        g_xk [o] = fmaf(xx, tm[2*NC+c]   + d2, xv);
        g_xv [o] = fmaf(xx, tm[3*NC+c]   + d3, xv);
    }
}

// ---------------- post: decay/exp, a/ma/mk sigmoids, kk normalize, k final, b ----------------
__global__ __launch_bounds__(256) void post_kernel(
    const float* __restrict__ td,  const float* __restrict__ tdw2,
    const float* __restrict__ ta5, const float* __restrict__ taw2,
    const float* __restrict__ tkw2,
    const float* __restrict__ tma_, const float* __restrict__ maw2,
    const float* __restrict__ tmk_, const float* __restrict__ mkw2)
{
    const int tok = blockIdx.x;
    const int tid = threadIdx.x;
    __shared__ float sw1[64], sa1[16], sma1[16], skk1[16], smk1[16];
    if (tid < 64)       sw1[tid]       = g_w1t[tok*64 + tid];
    else if (tid < 80)  sa1[tid-64]    = g_a1 [tok*16 + (tid-64)];
    else if (tid < 96)  sma1[tid-80]   = g_ma1[tok*16 + (tid-80)];
    else if (tid < 112) skk1[tid-96]   = g_kk1[tok*16 + (tid-96)];
    else if (tid < 128) smk1[tid-112]  = g_mk1[tok*16 + (tid-112)];
    __syncthreads();
    const size_t base = (size_t)tok*NC;
    float kkv[4], avv[4], ewv[4], kfv[4];
    float ss = 0.f;
    #pragma unroll
    for (int q = 0; q < 4; q++) {
        const int c = tid*4 + q;
        const float kraw = g_k[base + c];
        float u = td[c];
        const float* w2r = tdw2 + (size_t)c*64;
        #pragma unroll
        for (int d = 0; d < 64; d++) u = fmaf(sw1[d], w2r[d], u);
        float spz = -u;
        float sp = (spz > 15.f) ? spz : log1pf(expf(spz));
        float w = -sp - 0.5f;
        ewv[q] = expf(w);
        float ua  = ta5[c];  const float* ar  = taw2 + (size_t)c*16;
        float uma = tma_[c]; const float* mar = maw2 + (size_t)c*16;
        float umk = tmk_[c]; const float* mkr = mkw2 + (size_t)c*16;
        float uk  = 0.f;     const float* kr  = tkw2 + (size_t)c*16;
        #pragma unroll
        for (int d = 0; d < 16; d++) {
            ua  = fmaf(sa1[d],  ar[d],  ua);
            uma = fmaf(sma1[d], mar[d], uma);
            umk = fmaf(smk1[d], mkr[d], umk);
            uk  = fmaf(skk1[d], kr[d],  uk);
        }
        float a  = 1.f/(1.f + expf(-ua));
        float ma = 1.f/(1.f + expf(-uma));
        float mk = 1.f/(1.f + expf(-umk));
        avv[q] = a;
        float kq = kraw + uk;
        kkv[q] = kq;
        ss = fmaf(kq, kq, ss);
        kfv[q] = kraw * (ma + a*(1.f - ma)) * expf(w*mk);
    }
    ss += __shfl_xor_sync(0xffffffffu, ss, 1);
    ss += __shfl_xor_sync(0xffffffffu, ss, 2);
    ss += __shfl_xor_sync(0xffffffffu, ss, 4);
    ss += __shfl_xor_sync(0xffffffffu, ss, 8);
    const float rinv = 1.f / fmaxf(sqrtf(ss), 1e-12f);
    #pragma unroll
    for (int q = 0; q < 4; q++) {
        const int c = tid*4 + q;
        float kkn = kkv[q]*rinv;
        g_kkn[base+c] = kkn;
        g_bb [base+c] = -kkn*avv[q];
        g_ew [base+c] = ewv[q];
        g_kf [base+c] = kfv[q];
    }
}

// ---------------- RWKV-7 scan: one block per (b,h), 128 threads, 1 sync/step ----------------
__global__ __launch_bounds__(128) void scan_kernel()
{
    const int bh = blockIdx.x;
    const int b  = bh >> 4;
    const int h  = bh & 15;
    const int tid  = threadIdx.x;
    const int row  = tid >> 1;
    const int half = tid & 1;
    const int off  = half * 32;
    __shared__ __align__(16) float sbuf[2][6][64];
    float S[32];
    #pragma unroll
    for (int j = 0; j < 32; j++) S[j] = 0.f;
    const size_t base = ((size_t)b*NT)*NC + h*NNh;
    float pr=0.f, pe=0.f, pk=0.f, pv=0.f, pq=0.f, pb=0.f;
    if (tid < 64) {
        pr = g_r [base+tid]; pe = g_ew [base+tid]; pk = g_kf[base+tid];
        pv = g_v [base+tid]; pq = g_kkn[base+tid]; pb = g_bb[base+tid];
        sbuf[0][0][tid]=pr; sbuf[0][1][tid]=pe; sbuf[0][2][tid]=pk;
        sbuf[0][3][tid]=pv; sbuf[0][4][tid]=pq; sbuf[0][5][tid]=pb;
    }
    __syncthreads();
    for (int t = 0; t < NT; t++) {
        const int p = t & 1;
        // prefetch next step into registers (hides DRAM/L2 latency behind compute)
        if (t + 1 < NT && tid < 64) {
            const size_t nb = base + (size_t)(t+1)*NC;
            pr = g_r [nb+tid]; pe = g_ew [nb+tid]; pk = g_kf[nb+tid];
            pv = g_v [nb+tid]; pq = g_kkn[nb+tid]; pb = g_bb[nb+tid];
        }
        const float* sr = sbuf[p][0];
        const float* se = sbuf[p][1];
        const float* sk = sbuf[p][2];
        const float* sv = sbuf[p][3];
        const float* sq = sbuf[p][4];
        const float* sb = sbuf[p][5];
        const float4* q4 = (const float4*)(sq + off);
        float s0=0.f, s1=0.f, s2=0.f, s3=0.f;
        #pragma unroll
        for (int j = 0; j < 8; j++) {
            float4 q = q4[j];
            s0 = fmaf(S[4*j+0], q.x, s0);
            s1 = fmaf(S[4*j+1], q.y, s1);
            s2 = fmaf(S[4*j+2], q.z, s2);
            s3 = fmaf(S[4*j+3], q.w, s3);
        }
        float sab = (s0+s1)+(s2+s3);
        sab += __shfl_xor_sync(0xffffffffu, sab, 1);
        const float vv = sv[row];
        const float4* e4 = (const float4*)(se + off);
        const float4* b4 = (const float4*)(sb + off);
        const float4* k4 = (const float4*)(sk + off);
        const float4* r4 = (const float4*)(sr + off);
        float y0=0.f, y1=0.f, y2=0.f, y3=0.f;
        #pragma unroll
        for (int j = 0; j < 8; j++) {
            float4 e = e4[j], bv = b4[j], kv = k4[j], rv = r4[j];
            float t0 = fmaf(vv, kv.x, fmaf(sab, bv.x, S[4*j+0]*e.x));
            float t1 = fmaf(vv, kv.y, fmaf(sab, bv.y, S[4*j+1]*e.y));
            float t2 = fmaf(vv, kv.z, fmaf(sab, bv.z, S[4*j+2]*e.z));
            float t3 = fmaf(vv, kv.w, fmaf(sab, bv.w, S[4*j+3]*e.w));
            S[4*j+0]=t0; S[4*j+1]=t1; S[4*j+2]=t2; S[4*j+3]=t3;
            y0 = fmaf(t0, rv.x, y0);
            y1 = fmaf(t1, rv.y, y1);
            y2 = fmaf(t2, rv.z, y2);
            y3 = fmaf(t3, rv.w, y3);
        }
        float yv = (y0+y1)+(y2+y3);
        yv += __shfl_xor_sync(0xffffffffu, yv, 1);
        if (half == 0) g_y[base + (size_t)t*NC + row] = yv;
        // store prefetched next step into the other buffer (no reader conflict)
        if (t + 1 < NT && tid < 64) {
            float* nx0 = sbuf[p^1][0];
            nx0[tid]=pr; sbuf[p^1][1][tid]=pe; sbuf[p^1][2][tid]=pk;
            sbuf[p^1][3][tid]=pv; sbuf[p^1][4][tid]=pq; sbuf[p^1][5][tid]=pb;
        }
        __syncthreads();
    }
}

// ---------------- tail: GroupNorm + r.k bonus + gate ----------------
__global__ __launch_bounds__(256) void tail_kernel(
    const float* __restrict__ lnw, const float* __restrict__ lnb,
    const float* __restrict__ faaaa)
{
    const int tok = blockIdx.x;
    const int tid = threadIdx.x;
    const size_t base = (size_t)tok*NC;
    float yv[4], vv[4];
    float sy=0.f, syy=0.f, srk=0.f;
    #pragma unroll
    for (int q = 0; q < 4; q++) {
        const int c = tid*4 + q;
        float y = g_y[base+c];
        float r = g_r[base+c];
        float k = g_kf[base+c];
        vv[q] = g_v[base+c];
        yv[q] = y;
        sy += y;
        syy = fmaf(y, y, syy);
        srk = fmaf(r*k, faaaa[c], srk);
    }
    #pragma unroll
    for (int o = 1; o < 16; o <<= 1) {
        sy  += __shfl_xor_sync(0xffffffffu, sy,  o);
        syy += __shfl_xor_sync(0xffffffffu, syy, o);
        srk += __shfl_xor_sync(0xffffffffu, srk, o);
    }
    const float mu  = sy * (1.f/64.f);
    const float var = syy * (1.f/64.f) - mu*mu;
    const float inv = 1.f / sqrtf(var + 0.00064f);
    #pragma unroll
    for (int q = 0; q < 4; q++) {
        const int c = tid*4 + q;
        float yn = (yv[q] - mu) * inv * lnw[c] + lnb[c];
        g_z[base+c] = (yn + srk*vv[q]) * g_g[base+c];
    }
}

// ---------------- host ----------------
static inline void launch_big(const float* A, const float* W, float* C,
                              int M, int N, int K)
{
    dim3 grid(N/64, M/128);
    gemm_big_kernel<<<grid, 256>>>(A, W, C, M, N, K);
}
static inline void launch_thin(const float* A, const float* W, float* C,
                               int M, int N, int K, int act)
{
    dim3 grid(M/32, (N + 31)/32);
    gemm_thin_kernel<<<grid, 256>>>(A, W, C, N, K, act);
}

extern "C" void kernel_launch(void* const* d_in, const int* in_sizes, int n_in,
                              void* d_out, int out_size)
{
    const float* x     = (const float*)d_in[0];
    const float* tmx   = (const float*)d_in[1];
    const float* tm    = (const float*)d_in[2];
    const float* maaw1 = (const float*)d_in[3];
    const float* maaw2 = (const float*)d_in[4];
    const float* td    = (const float*)d_in[5];
    const float* tdw1  = (const float*)d_in[6];
    const float* tdw2  = (const float*)d_in[7];
    const float* ta5   = (const float*)d_in[8];
    const float* taw1  = (const float*)d_in[9];
    const float* taw2  = (const float*)d_in[10];
    const float* tkw1  = (const float*)d_in[11];
    const float* tkw2  = (const float*)d_in[12];
    const float* gw1   = (const float*)d_in[13];
    const float* gw2   = (const float*)d_in[14];
    const float* tma_  = (const float*)d_in[15];
    const float* maw1  = (const float*)d_in[16];
    const float* maw2  = (const float*)d_in[17];
    const float* tmk_  = (const float*)d_in[18];
    const float* mkw1  = (const float*)d_in[19];
    const float* mkw2  = (const float*)d_in[20];
    const float* recw  = (const float*)d_in[21];
    const float* keyw  = (const float*)d_in[22];
    const float* valw  = (const float*)d_in[23];
    const float* outw  = (const float*)d_in[24];
    const float* lnw   = (const float*)d_in[25];
    const float* lnb   = (const float*)d_in[26];
    const float* faaaa = (const float*)d_in[27];
    float* out = (float*)d_out;

    float *p_xxx, *p_mixh, *p_xrg, *p_xwa, *p_xk, *p_xv;
    float *p_r, *p_k, *p_v, *p_w1t, *p_a1, *p_ma1, *p_kk1, *p_mk1, *p_g1, *p_g, *p_z;
    cudaGetSymbolAddress((void**)&p_xxx,  g_xxx);
    cudaGetSymbolAddress((void**)&p_mixh, g_mixh);
    cudaGetSymbolAddress((void**)&p_xrg,  g_xrg);
    cudaGetSymbolAddress((void**)&p_xwa,  g_xwa);
    cudaGetSymbolAddress((void**)&p_xk,   g_xk);
    cudaGetSymbolAddress((void**)&p_xv,   g_xv);
    cudaGetSymbolAddress((void**)&p_r,    g_r);
    cudaGetSymbolAddress((void**)&p_k,    g_k);
    cudaGetSymbolAddress((void**)&p_v,    g_v);
    cudaGetSymbolAddress((void**)&p_w1t,  g_w1t);
    cudaGetSymbolAddress((void**)&p_a1,   g_a1);
    cudaGetSymbolAddress((void**)&p_ma1,  g_ma1);
    cudaGetSymbolAddress((void**)&p_kk1,  g_kk1);
    cudaGetSymbolAddress((void**)&p_mk1,  g_mk1);
    cudaGetSymbolAddress((void**)&p_g1,   g_g1);
    cudaGetSymbolAddress((void**)&p_g,    g_g);
    cudaGetSymbolAddress((void**)&p_z,    g_z);

    // 1. token shift
    shift_kernel<<<(NBT*NC)/256, 256>>>(x, tmx);
    // 2. mix hidden = tanh(xxx @ maa_w1^T)   (2048x128, K=1024)
    launch_thin(p_xxx, maaw1, p_mixh, NBT, 128, NC, 1);
    // 3. apply 4-way mixing -> xrg, xwa, xk, xv
    mix_apply_kernel<<<NBT, 256>>>(x, tm, maaw2);
    // 4. big projections
    launch_big(p_xrg, recw, p_r, NBT, NC, NC);
    launch_big(p_xk,  keyw, p_k, NBT, NC, NC);
    launch_big(p_xv,  valw, p_v, NBT, NC, NC);
    // 5. LoRA hiddens (thin)
    launch_thin(p_xwa, tdw1, p_w1t, NBT, 64,  NC, 1);  // tanh
    launch_thin(p_xwa, taw1, p_a1,  NBT, 16,  NC, 0);
    launch_thin(p_xwa, maw1, p_ma1, NBT, 16,  NC, 0);
    launch_thin(p_xk,  tkw1, p_kk1, NBT, 16,  NC, 1);  // tanh
    launch_thin(p_xk,  mkw1, p_mk1, NBT, 16,  NC, 0);
    launch_thin(p_xrg, gw1,  p_g1,  NBT, 128, NC, 1);  // tanh
    // 6. gate g = g1 @ gate_w2^T  (K=128)
    launch_big(p_g1, gw2, p_g, NBT, NC, 128);
    // 7. elementwise post: ew, kk_norm, k_final, b
    post_kernel<<<NBT, 256>>>(td, tdw2, ta5, taw2, tkw2, tma_, maw2, tmk_, mkw2);
    // 8. RWKV-7 scan
    scan_kernel<<<NB*NH, 128>>>();
    // 9. GroupNorm + bonus + gate
    tail_kernel<<<NBT, 256>>>(lnw, lnb, faaaa);
    // 10. output projection
    launch_big(p_z, outw, out, NBT, NC, NC);

    (void)in_sizes; (void)n_in; (void)out_size; (void)tdw1;
}

// round 5
// speedup vs baseline: 1.2776x; 1.0688x over previous
#include <cuda_runtime.h>
#include <math.h>

#define NB 2
#define NT 1024
#define NC 1024
#define NH 16
#define NNh 64
#define NBT (NB*NT)
#define CH 16
#define NCH (NT/CH)

// ---------------- scratch (device globals; no allocation allowed) ----------------
__device__ float g_xxx[NBT*NC];
__device__ float g_mixh[NBT*128];
__device__ float g_xrg[NBT*NC];
__device__ float g_xwa[NBT*NC];
__device__ float g_xk [NBT*NC];
__device__ float g_xv [NBT*NC];
__device__ float g_r  [NBT*NC];
__device__ float g_k  [NBT*NC];
__device__ float g_v  [NBT*NC];
__device__ float g_w1t[NBT*64];
__device__ float g_a1 [NBT*16];
__device__ float g_ma1[NBT*16];
__device__ float g_kk1[NBT*16];
__device__ float g_mk1[NBT*16];
__device__ float g_g1 [NBT*128];
__device__ float g_g  [NBT*NC];
__device__ float g_ew [NBT*NC];
__device__ float g_kf [NBT*NC];
__device__ float g_kkn[NBT*NC];
__device__ float g_bb [NBT*NC];
__device__ float g_y  [NBT*NC];
__device__ float g_z  [NBT*NC];

// ---------------- packed f32x2 helpers ----------------
__device__ __forceinline__ unsigned long long pk2(float lo, float hi) {
    unsigned long long r;
    asm("mov.b64 %0, {%1, %2};" : "=l"(r) : "f"(lo), "f"(hi));
    return r;
}
__device__ __forceinline__ void fma2(unsigned long long& d, unsigned long long a, unsigned long long b) {
    asm("fma.rn.f32x2 %0, %1, %2, %0;" : "+l"(d) : "l"(a), "l"(b));
}
__device__ __forceinline__ unsigned long long mul2(unsigned long long a, unsigned long long b) {
    unsigned long long r;
    asm("mul.rn.f32x2 %0, %1, %2;" : "=l"(r) : "l"(a), "l"(b));
    return r;
}
__device__ __forceinline__ float2 up2(unsigned long long a) {
    float2 f;
    asm("mov.b64 {%0, %1}, %2;" : "=f"(f.x), "=f"(f.y) : "l"(a));
    return f;
}

// ---------------- BIG GEMM: C = A(MxK) @ W(NxK)^T, 128x64 tile ----------------
__global__ __launch_bounds__(256, 2) void gemm_big_kernel(
    const float* __restrict__ A, const float* __restrict__ W, float* __restrict__ C,
    int M, int N, int K)
{
    __shared__ __align__(16) float As[16][132];
    __shared__ __align__(16) float Ws[16][68];
    const int bm = blockIdx.y * 128;
    const int bn = blockIdx.x * 64;
    const int tid = threadIdx.x;
    const int tx = tid & 15;
    const int ty = tid >> 4;
    const int lr = tid >> 1;
    const int lka = (tid & 1) * 8;
    const int wr = tid >> 2;
    const int wka = (tid & 3) * 4;

    unsigned long long acc[8][2];
    #pragma unroll
    for (int i = 0; i < 8; i++) { acc[i][0] = 0ull; acc[i][1] = 0ull; }

    for (int k0 = 0; k0 < K; k0 += 16) {
        float4 a0 = *(const float4*)(A + (size_t)(bm+lr)*K + k0 + lka);
        float4 a1 = *(const float4*)(A + (size_t)(bm+lr)*K + k0 + lka + 4);
        float4 wv = *(const float4*)(W + (size_t)(bn+wr)*K + k0 + wka);
        As[lka+0][lr]=a0.x; As[lka+1][lr]=a0.y; As[lka+2][lr]=a0.z; As[lka+3][lr]=a0.w;
        As[lka+4][lr]=a1.x; As[lka+5][lr]=a1.y; As[lka+6][lr]=a1.z; As[lka+7][lr]=a1.w;
        Ws[wka+0][wr]=wv.x; Ws[wka+1][wr]=wv.y; Ws[wka+2][wr]=wv.z; Ws[wka+3][wr]=wv.w;
        __syncthreads();
        #pragma unroll
        for (int kk = 0; kk < 16; kk++) {
            float4 f0 = *(const float4*)&As[kk][ty*8];
            float4 f1 = *(const float4*)&As[kk][ty*8+4];
            ulonglong2 q = *(const ulonglong2*)&Ws[kk][tx*4];
            float a8[8] = {f0.x,f0.y,f0.z,f0.w,f1.x,f1.y,f1.z,f1.w};
            #pragma unroll
            for (int i = 0; i < 8; i++) {
                unsigned long long ad = pk2(a8[i], a8[i]);
                fma2(acc[i][0], ad, q.x);
                fma2(acc[i][1], ad, q.y);
            }
        }
        __syncthreads();
    }
    #pragma unroll
    for (int i = 0; i < 8; i++) {
        int m = bm + ty*8 + i;
        float2 f0 = *(float2*)&acc[i][0];
        float2 f1 = *(float2*)&acc[i][1];
        float4 o = make_float4(f0.x, f0.y, f1.x, f1.y);
        *(float4*)(C + (size_t)m*N + bn + tx*4) = o;
    }
}

// ---------------- THIN GEMM: C = A(MxK) @ W(NxK)^T, N<=128, 32x32 tile ----------------
__global__ __launch_bounds__(256) void gemm_thin_kernel(
    const float* __restrict__ A, const float* __restrict__ W, float* __restrict__ C,
    int N, int K, int act)
{
    __shared__ float As[32][33];
    __shared__ __align__(16) float Ws[32][36];
    const int bm = blockIdx.x * 32;
    const int bn = blockIdx.y * 32;
    const int tid = threadIdx.x;
    const int lr = tid >> 3;
    const int lk = (tid & 7) * 4;
    const int ty = tid >> 3;
    const int tx = tid & 7;

    float acc0=0.f, acc1=0.f, acc2=0.f, acc3=0.f;
    const int wrow = bn + lr;

    for (int k0 = 0; k0 < K; k0 += 32) {
        float4 av = *(const float4*)(A + (size_t)(bm+lr)*K + k0 + lk);
        float4 wv = make_float4(0.f,0.f,0.f,0.f);
        if (wrow < N) wv = *(const float4*)(W + (size_t)wrow*K + k0 + lk);
        As[lk+0][lr]=av.x; As[lk+1][lr]=av.y; As[lk+2][lr]=av.z; As[lk+3][lr]=av.w;
        Ws[lk+0][lr]=wv.x; Ws[lk+1][lr]=wv.y; Ws[lk+2][lr]=wv.z; Ws[lk+3][lr]=wv.w;
        __syncthreads();
        #pragma unroll
        for (int kk = 0; kk < 32; kk++) {
            float a = As[kk][ty];
            float4 w4 = *(const float4*)&Ws[kk][tx*4];
            acc0 = fmaf(a, w4.x, acc0);
            acc1 = fmaf(a, w4.y, acc1);
            acc2 = fmaf(a, w4.z, acc2);
            acc3 = fmaf(a, w4.w, acc3);
        }
        __syncthreads();
    }
    if (act) { acc0=tanhf(acc0); acc1=tanhf(acc1); acc2=tanhf(acc2); acc3=tanhf(acc3); }
    const int m = bm + ty;
    const int n0 = bn + tx*4;
    float* cr = C + (size_t)m*N;
    if (n0   < N) cr[n0]   = acc0;
    if (n0+1 < N) cr[n0+1] = acc1;
    if (n0+2 < N) cr[n0+2] = acc2;
    if (n0+3 < N) cr[n0+3] = acc3;
}

// ---------------- token shift ----------------
__global__ __launch_bounds__(256) void shift_kernel(const float* __restrict__ x,
                                                    const float* __restrict__ tmx)
{
    const size_t i = (size_t)blockIdx.x*256 + threadIdx.x;
    const int c = (int)(i & (NC-1));
    const size_t tok = i >> 10;
    const int tt = (int)(tok & (NT-1));
    float xv = x[i];
    float xp = (tt == 0) ? 0.f : x[i - NC];
    g_xxx[i] = fmaf(xp - xv, tmx[c], xv);
}

// ---------------- 4-way LoRA mix apply ----------------
__global__ __launch_bounds__(256) void mix_apply_kernel(
    const float* __restrict__ x, const float* __restrict__ tm,
    const float* __restrict__ w2)
{
    const int tok = blockIdx.x;
    const int tid = threadIdx.x;
    __shared__ float mh[128];
    if (tid < 128) mh[tid] = g_mixh[tok*128 + tid];
    __syncthreads();
    const int tt = tok & (NT-1);
    const float* xr = x + (size_t)tok*NC;
    #pragma unroll
    for (int it = 0; it < 4; it++) {
        const int c = tid + it*256;
        float xv = xr[c];
        float xp = (tt == 0) ? 0.f : xr[c - NC];
        float xx = xp - xv;
        float d0=0.f, d1=0.f, d2=0.f, d3=0.f;
        const float* w0 = w2 + (size_t)0*NC*32 + (size_t)c*32;
        const float* w1 = w2 + (size_t)1*NC*32 + (size_t)c*32;
        const float* wq = w2 + (size_t)2*NC*32 + (size_t)c*32;
        const float* w3 = w2 + (size_t)3*NC*32 + (size_t)c*32;
        #pragma unroll
        for (int d = 0; d < 32; d++) {
            d0 = fmaf(mh[d],      w0[d], d0);
            d1 = fmaf(mh[32+d],   w1[d], d1);
            d2 = fmaf(mh[64+d],   wq[d], d2);
            d3 = fmaf(mh[96+d],   w3[d], d3);
        }
        const size_t o = (size_t)tok*NC + c;
        g_xrg[o] = fmaf(xx, tm[c]        + d0, xv);
        g_xwa[o] = fmaf(xx, tm[NC+c]     + d1, xv);
        g_xk [o] = fmaf(xx, tm[2*NC+c]   + d2, xv);
        g_xv [o] = fmaf(xx, tm[3*NC+c]   + d3, xv);
    }
}

// ---------------- post: decay/exp, sigmoids, kk normalize, k final, b ----------------
__global__ __launch_bounds__(256) void post_kernel(
    const float* __restrict__ td,  const float* __restrict__ tdw2,
    const float* __restrict__ ta5, const float* __restrict__ taw2,
    const float* __restrict__ tkw2,
    const float* __restrict__ tma_, const float* __restrict__ maw2,
    const float* __restrict__ tmk_, const float* __restrict__ mkw2)
{
    const int tok = blockIdx.x;
    const int tid = threadIdx.x;
    __shared__ float sw1[64], sa1[16], sma1[16], skk1[16], smk1[16];
    if (tid < 64)       sw1[tid]       = g_w1t[tok*64 + tid];
    else if (tid < 80)  sa1[tid-64]    = g_a1 [tok*16 + (tid-64)];
    else if (tid < 96)  sma1[tid-80]   = g_ma1[tok*16 + (tid-80)];
    else if (tid < 112) skk1[tid-96]   = g_kk1[tok*16 + (tid-96)];
    else if (tid < 128) smk1[tid-112]  = g_mk1[tok*16 + (tid-112)];
    __syncthreads();
    const size_t base = (size_t)tok*NC;
    float kkv[4], avv[4], ewv[4], kfv[4];
    float ss = 0.f;
    #pragma unroll
    for (int q = 0; q < 4; q++) {
        const int c = tid*4 + q;
        const float kraw = g_k[base + c];
        float u = td[c];
        const float* w2r = tdw2 + (size_t)c*64;
        #pragma unroll
        for (int d = 0; d < 64; d++) u = fmaf(sw1[d], w2r[d], u);
        float spz = -u;
        float sp = (spz > 15.f) ? spz : log1pf(expf(spz));
        float w = -sp - 0.5f;
        ewv[q] = expf(w);
        float ua  = ta5[c];  const float* ar  = taw2 + (size_t)c*16;
        float uma = tma_[c]; const float* mar = maw2 + (size_t)c*16;
        float umk = tmk_[c]; const float* mkr = mkw2 + (size_t)c*16;
        float uk  = 0.f;     const float* kr  = tkw2 + (size_t)c*16;
        #pragma unroll
        for (int d = 0; d < 16; d++) {
            ua  = fmaf(sa1[d],  ar[d],  ua);
            uma = fmaf(sma1[d], mar[d], uma);
            umk = fmaf(smk1[d], mkr[d], umk);
            uk  = fmaf(skk1[d], kr[d],  uk);
        }
        float a  = 1.f/(1.f + expf(-ua));
        float ma = 1.f/(1.f + expf(-uma));
        float mk = 1.f/(1.f + expf(-umk));
        avv[q] = a;
        float kq = kraw + uk;
        kkv[q] = kq;
        ss = fmaf(kq, kq, ss);
        kfv[q] = kraw * (ma + a*(1.f - ma)) * expf(w*mk);
    }
    ss += __shfl_xor_sync(0xffffffffu, ss, 1);
    ss += __shfl_xor_sync(0xffffffffu, ss, 2);
    ss += __shfl_xor_sync(0xffffffffu, ss, 4);
    ss += __shfl_xor_sync(0xffffffffu, ss, 8);
    const float rinv = 1.f / fmaxf(sqrtf(ss), 1e-12f);
    #pragma unroll
    for (int q = 0; q < 4; q++) {
        const int c = tid*4 + q;
        float kkn = kkv[q]*rinv;
        g_kkn[base+c] = kkn;
        g_bb [base+c] = -kkn*avv[q];
        g_ew [base+c] = ewv[q];
        g_kf [base+c] = kfv[q];
    }
}

// ---------------- RWKV-7 scan: chunked, f32x2, row-split ----------------
// 64 blocks = (b,h) x 2 row-halves. 128 threads: 32 rows x 4 threads (16 cols each).
// Chunks of CH=16 steps staged through double-buffered smem; 1 barrier per chunk.
#define LOAD_ARR(arr, G) { \
    const int i0 = tid, i1 = tid + 128; \
    pf[2*(arr)+0] = *(const float4*)((G) + gb + (size_t)(i0>>4)*NC + ((i0&15)<<2)); \
    pf[2*(arr)+1] = *(const float4*)((G) + gb + (size_t)(i1>>4)*NC + ((i1&15)<<2)); }
#define STORE_ARR(arr, dst) { \
    const int i0 = tid, i1 = tid + 128; \
    *(float4*)&cbuf[dst][arr][i0>>4][(i0&15)<<2] = pf[2*(arr)+0]; \
    *(float4*)&cbuf[dst][arr][i1>>4][(i1&15)<<2] = pf[2*(arr)+1]; }

__global__ __launch_bounds__(128) void scan_kernel()
{
    const int blk = blockIdx.x;
    const int bh  = blk >> 1;
    const int rh  = blk & 1;
    const int b   = bh >> 4;
    const int h   = bh & 15;
    const int tid = threadIdx.x;
    const int row = rh*32 + (tid >> 2);   // 0..63 within head
    const int sub = tid & 3;
    const int coff = sub * 16;            // 16 cols per thread

    // arrays: 0=r 1=ew 2=kf 3=v 4=kkn 5=bb   (exactly 48KB)
    __shared__ __align__(16) float cbuf[2][6][CH][64];

    unsigned long long S[8];              // 16 state cols as 8 f32x2 pairs
    #pragma unroll
    for (int j = 0; j < 8; j++) S[j] = 0ull;

    const size_t base = ((size_t)b*NT)*NC + (size_t)h*NNh;

    // prefill chunk 0
    {
        const size_t gb = base;
        float4 pf[12];
        LOAD_ARR(0, g_r);  LOAD_ARR(1, g_ew); LOAD_ARR(2, g_kf);
        LOAD_ARR(3, g_v);  LOAD_ARR(4, g_kkn); LOAD_ARR(5, g_bb);
        STORE_ARR(0, 0); STORE_ARR(1, 0); STORE_ARR(2, 0);
        STORE_ARR(3, 0); STORE_ARR(4, 0); STORE_ARR(5, 0);
    }
    __syncthreads();

    for (int c = 0; c < NCH; c++) {
        const int buf = c & 1;
        const int nb  = buf ^ 1;
        float4 pf[12];
        if (c + 1 < NCH) {
            const size_t gb = base + (size_t)((c+1)*CH)*NC;
            LOAD_ARR(0, g_r);  LOAD_ARR(1, g_ew); LOAD_ARR(2, g_kf);
            LOAD_ARR(3, g_v);  LOAD_ARR(4, g_kkn); LOAD_ARR(5, g_bb);
        }
        const size_t ybase = base + (size_t)(c*CH)*NC + row;
        #pragma unroll 4
        for (int s = 0; s < CH; s++) {
            const ulonglong2* rp  = (const ulonglong2*)&cbuf[buf][0][s][coff];
            const ulonglong2* ewp = (const ulonglong2*)&cbuf[buf][1][s][coff];
            const ulonglong2* kfp = (const ulonglong2*)&cbuf[buf][2][s][coff];
            const ulonglong2* kkp = (const ulonglong2*)&cbuf[buf][4][s][coff];
            const ulonglong2* bbp = (const ulonglong2*)&cbuf[buf][5][s][coff];
            const float vv = cbuf[buf][3][s][row];
            // sab partial = dot(S_row[coff..coff+16), kk)
            unsigned long long a0 = 0ull, a1 = 0ull;
            #pragma unroll
            for (int j = 0; j < 4; j++) {
                ulonglong2 kq = kkp[j];
                fma2(a0, S[2*j+0], kq.x);
                fma2(a1, S[2*j+1], kq.y);
            }
            float2 fa0 = up2(a0), fa1 = up2(a1);
            float sab = (fa0.x + fa0.y) + (fa1.x + fa1.y);
            sab += __shfl_xor_sync(0xffffffffu, sab, 1);
            sab += __shfl_xor_sync(0xffffffffu, sab, 2);
            const unsigned long long sab2 = pk2(sab, sab);
            const unsigned long long vv2  = pk2(vv, vv);
            unsigned long long y0 = 0ull, y1 = 0ull;
            #pragma unroll
            for (int j = 0; j < 4; j++) {
                ulonglong2 eq = ewp[j], bq = bbp[j], kq = kfp[j], rq = rp[j];
                unsigned long long t0 = mul2(S[2*j+0], eq.x);
                fma2(t0, sab2, bq.x);
                fma2(t0, vv2,  kq.x);
                S[2*j+0] = t0;
                fma2(y0, t0, rq.x);
                unsigned long long t1 = mul2(S[2*j+1], eq.y);
                fma2(t1, sab2, bq.y);
                fma2(t1, vv2,  kq.y);
                S[2*j+1] = t1;
                fma2(y1, t1, rq.y);
            }
            float2 fy0 = up2(y0), fy1 = up2(y1);
            float yv = (fy0.x + fy0.y) + (fy1.x + fy1.y);
            yv += __shfl_xor_sync(0xffffffffu, yv, 1);
            yv += __shfl_xor_sync(0xffffffffu, yv, 2);
            if (sub == 0) g_y[ybase + (size_t)s*NC] = yv;
        }
        if (c + 1 < NCH) {
            STORE_ARR(0, nb); STORE_ARR(1, nb); STORE_ARR(2, nb);
            STORE_ARR(3, nb); STORE_ARR(4, nb); STORE_ARR(5, nb);
        }
        __syncthreads();
    }
}

// ---------------- tail: GroupNorm + r.k bonus + gate ----------------
__global__ __launch_bounds__(256) void tail_kernel(
    const float* __restrict__ lnw, const float* __restrict__ lnb,
    const float* __restrict__ faaaa)
{
    const int tok = blockIdx.x;
    const int tid = threadIdx.x;
    const size_t base = (size_t)tok*NC;
    float yv[4], vv[4];
    float sy=0.f, syy=0.f, srk=0.f;
    #pragma unroll
    for (int q = 0; q < 4; q++) {
        const int c = tid*4 + q;
        float y = g_y[base+c];
        float r = g_r[base+c];
        float k = g_kf[base+c];
        vv[q] = g_v[base+c];
        yv[q] = y;
        sy += y;
        syy = fmaf(y, y, syy);
        srk = fmaf(r*k, faaaa[c], srk);
    }
    #pragma unroll
    for (int o = 1; o < 16; o <<= 1) {
        sy  += __shfl_xor_sync(0xffffffffu, sy,  o);
        syy += __shfl_xor_sync(0xffffffffu, syy, o);
        srk += __shfl_xor_sync(0xffffffffu, srk, o);
    }
    const float mu  = sy * (1.f/64.f);
    const float var = syy * (1.f/64.f) - mu*mu;
    const float inv = 1.f / sqrtf(var + 0.00064f);
    #pragma unroll
    for (int q = 0; q < 4; q++) {
        const int c = tid*4 + q;
        float yn = (yv[q] - mu) * inv * lnw[c] + lnb[c];
        g_z[base+c] = (yn + srk*vv[q]) * g_g[base+c];
    }
}

// ---------------- host ----------------
static inline void launch_big(const float* A, const float* W, float* C,
                              int M, int N, int K)
{
    dim3 grid(N/64, M/128);
    gemm_big_kernel<<<grid, 256>>>(A, W, C, M, N, K);
}
static inline void launch_thin(const float* A, const float* W, float* C,
                               int M, int N, int K, int act)
{
    dim3 grid(M/32, (N + 31)/32);
    gemm_thin_kernel<<<grid, 256>>>(A, W, C, N, K, act);
}

extern "C" void kernel_launch(void* const* d_in, const int* in_sizes, int n_in,
                              void* d_out, int out_size)
{
    const float* x     = (const float*)d_in[0];
    const float* tmx   = (const float*)d_in[1];
    const float* tm    = (const float*)d_in[2];
    const float* maaw1 = (const float*)d_in[3];
    const float* maaw2 = (const float*)d_in[4];
    const float* td    = (const float*)d_in[5];
    const float* tdw1  = (const float*)d_in[6];
    const float* tdw2  = (const float*)d_in[7];
    const float* ta5   = (const float*)d_in[8];
    const float* taw1  = (const float*)d_in[9];
    const float* taw2  = (const float*)d_in[10];
    const float* tkw1  = (const float*)d_in[11];
    const float* tkw2  = (const float*)d_in[12];
    const float* gw1   = (const float*)d_in[13];
    const float* gw2   = (const float*)d_in[14];
    const float* tma_  = (const float*)d_in[15];
    const float* maw1  = (const float*)d_in[16];
    const float* maw2  = (const float*)d_in[17];
    const float* tmk_  = (const float*)d_in[18];
    const float* mkw1  = (const float*)d_in[19];
    const float* mkw2  = (const float*)d_in[20];
    const float* recw  = (const float*)d_in[21];
    const float* keyw  = (const float*)d_in[22];
    const float* valw  = (const float*)d_in[23];
    const float* outw  = (const float*)d_in[24];
    const float* lnw   = (const float*)d_in[25];
    const float* lnb   = (const float*)d_in[26];
    const float* faaaa = (const float*)d_in[27];
    float* out = (float*)d_out;

    float *p_xxx, *p_mixh, *p_xrg, *p_xwa, *p_xk, *p_xv;
    float *p_r, *p_k, *p_v, *p_w1t, *p_a1, *p_ma1, *p_kk1, *p_mk1, *p_g1, *p_g, *p_z;
    cudaGetSymbolAddress((void**)&p_xxx,  g_xxx);
    cudaGetSymbolAddress((void**)&p_mixh, g_mixh);
    cudaGetSymbolAddress((void**)&p_xrg,  g_xrg);
    cudaGetSymbolAddress((void**)&p_xwa,  g_xwa);
    cudaGetSymbolAddress((void**)&p_xk,   g_xk);
    cudaGetSymbolAddress((void**)&p_xv,   g_xv);
    cudaGetSymbolAddress((void**)&p_r,    g_r);
    cudaGetSymbolAddress((void**)&p_k,    g_k);
    cudaGetSymbolAddress((void**)&p_v,    g_v);
    cudaGetSymbolAddress((void**)&p_w1t,  g_w1t);
    cudaGetSymbolAddress((void**)&p_a1,   g_a1);
    cudaGetSymbolAddress((void**)&p_ma1,  g_ma1);
    cudaGetSymbolAddress((void**)&p_kk1,  g_kk1);
    cudaGetSymbolAddress((void**)&p_mk1,  g_mk1);
    cudaGetSymbolAddress((void**)&p_g1,   g_g1);
    cudaGetSymbolAddress((void**)&p_g,    g_g);
    cudaGetSymbolAddress((void**)&p_z,    g_z);

    // 1. token shift
    shift_kernel<<<(NBT*NC)/256, 256>>>(x, tmx);
    // 2. mix hidden = tanh(xxx @ maa_w1^T)
    launch_thin(p_xxx, maaw1, p_mixh, NBT, 128, NC, 1);
    // 3. apply 4-way mixing -> xrg, xwa, xk, xv
    mix_apply_kernel<<<NBT, 256>>>(x, tm, maaw2);
    // 4. big projections
    launch_big(p_xrg, recw, p_r, NBT, NC, NC);
    launch_big(p_xk,  keyw, p_k, NBT, NC, NC);
    launch_big(p_xv,  valw, p_v, NBT, NC, NC);
    // 5. LoRA hiddens (thin)
    launch_thin(p_xwa, tdw1, p_w1t, NBT, 64,  NC, 1);
    launch_thin(p_xwa, taw1, p_a1,  NBT, 16,  NC, 0);
    launch_thin(p_xwa, maw1, p_ma1, NBT, 16,  NC, 0);
    launch_thin(p_xk,  tkw1, p_kk1, NBT, 16,  NC, 1);
    launch_thin(p_xk,  mkw1, p_mk1, NBT, 16,  NC, 0);
    launch_thin(p_xrg, gw1,  p_g1,  NBT, 128, NC, 1);
    // 6. gate g = g1 @ gate_w2^T
    launch_big(p_g1, gw2, p_g, NBT, NC, 128);
    // 7. elementwise post
    post_kernel<<<NBT, 256>>>(td, tdw2, ta5, taw2, tkw2, tma_, maw2, tmk_, mkw2);
    // 8. RWKV-7 scan (chunked, row-split)
    scan_kernel<<<NB*NH*2, 128>>>();
    // 9. GroupNorm + bonus + gate
    tail_kernel<<<NBT, 256>>>(lnw, lnb, faaaa);
    // 10. output projection
    launch_big(p_z, outw, out, NBT, NC, NC);

    (void)in_sizes; (void)n_in; (void)out_size; (void)tdw1;
}

// round 6
// speedup vs baseline: 3.0331x; 2.3741x over previous
#include <cuda_runtime.h>
#include <math.h>

#define NB 2
#define NT 1024
#define NC 1024
#define NH 16
#define NNh 64
#define NBT (NB*NT)
#define CH 16
#define NCH (NT/CH)

// ---------------- scratch (device globals; no allocation allowed) ----------------
__device__ float g_xxx[NBT*NC];
__device__ float g_mixh[NBT*128];
__device__ float g_xrg[NBT*NC];
__device__ float g_xwa[NBT*NC];
__device__ float g_xk [NBT*NC];
__device__ float g_xv [NBT*NC];
__device__ float g_r  [NBT*NC];
__device__ float g_k  [NBT*NC];
__device__ float g_v  [NBT*NC];
__device__ float g_w1t[NBT*64];
__device__ float g_a1 [NBT*16];
__device__ float g_ma1[NBT*16];
__device__ float g_kk1[NBT*16];
__device__ float g_mk1[NBT*16];
__device__ float g_g1 [NBT*128];
__device__ float g_g  [NBT*NC];
__device__ float g_ew [NBT*NC];
__device__ float g_kf [NBT*NC];
__device__ float g_kkn[NBT*NC];
__device__ float g_bb [NBT*NC];
__device__ float g_y  [NBT*NC];
__device__ float g_z  [NBT*NC];
// delta buffers (LoRA second stages, computed as GEMMs)
__device__ float g_dw [NBT*NC];
__device__ float g_da [NBT*NC];
__device__ float g_dma[NBT*NC];
__device__ float g_dkk[NBT*NC];
__device__ float g_dmk[NBT*NC];

// ---------------- packed f32x2 helpers ----------------
__device__ __forceinline__ unsigned long long pk2(float lo, float hi) {
    unsigned long long r;
    asm("mov.b64 %0, {%1, %2};" : "=l"(r) : "f"(lo), "f"(hi));
    return r;
}
__device__ __forceinline__ void fma2(unsigned long long& d, unsigned long long a, unsigned long long b) {
    asm("fma.rn.f32x2 %0, %1, %2, %0;" : "+l"(d) : "l"(a), "l"(b));
}
__device__ __forceinline__ unsigned long long mul2(unsigned long long a, unsigned long long b) {
    unsigned long long r;
    asm("mul.rn.f32x2 %0, %1, %2;" : "=l"(r) : "l"(a), "l"(b));
    return r;
}
__device__ __forceinline__ float2 up2(unsigned long long a) {
    float2 f;
    asm("mov.b64 {%0, %1}, %2;" : "=f"(f.x), "=f"(f.y) : "l"(a));
    return f;
}

// ---------------- BIG GEMM: C(Mx1024) = A(MxK,lda) @ W(1024xK,ldw)^T ----------------
// mode 0: C = acc
// mode 1: C = x + (xprev - x) * (tmf + acc)    (token-shift mix epilogue)
__global__ __launch_bounds__(256, 2) void gemm_big_kernel(
    const float* __restrict__ A, int lda,
    const float* __restrict__ W, int ldw,
    float* __restrict__ C, int K,
    const float* __restrict__ xin, const float* __restrict__ tmf, int mode)
{
    __shared__ __align__(16) float As[16][132];
    __shared__ __align__(16) float Ws[16][68];
    const int bm = blockIdx.y * 128;
    const int bn = blockIdx.x * 64;
    const int tid = threadIdx.x;
    const int tx = tid & 15;
    const int ty = tid >> 4;
    const int lr = tid >> 1;
    const int lka = (tid & 1) * 8;
    const int wr = tid >> 2;
    const int wka = (tid & 3) * 4;

    unsigned long long acc[8][2];
    #pragma unroll
    for (int i = 0; i < 8; i++) { acc[i][0] = 0ull; acc[i][1] = 0ull; }

    for (int k0 = 0; k0 < K; k0 += 16) {
        float4 a0 = *(const float4*)(A + (size_t)(bm+lr)*lda + k0 + lka);
        float4 a1 = *(const float4*)(A + (size_t)(bm+lr)*lda + k0 + lka + 4);
        float4 wv = *(const float4*)(W + (size_t)(bn+wr)*ldw + k0 + wka);
        As[lka+0][lr]=a0.x; As[lka+1][lr]=a0.y; As[lka+2][lr]=a0.z; As[lka+3][lr]=a0.w;
        As[lka+4][lr]=a1.x; As[lka+5][lr]=a1.y; As[lka+6][lr]=a1.z; As[lka+7][lr]=a1.w;
        Ws[wka+0][wr]=wv.x; Ws[wka+1][wr]=wv.y; Ws[wka+2][wr]=wv.z; Ws[wka+3][wr]=wv.w;
        __syncthreads();
        #pragma unroll
        for (int kk = 0; kk < 16; kk++) {
            float4 f0 = *(const float4*)&As[kk][ty*8];
            float4 f1 = *(const float4*)&As[kk][ty*8+4];
            ulonglong2 q = *(const ulonglong2*)&Ws[kk][tx*4];
            float a8[8] = {f0.x,f0.y,f0.z,f0.w,f1.x,f1.y,f1.z,f1.w};
            #pragma unroll
            for (int i = 0; i < 8; i++) {
                unsigned long long ad = pk2(a8[i], a8[i]);
                fma2(acc[i][0], ad, q.x);
                fma2(acc[i][1], ad, q.y);
            }
        }
        __syncthreads();
    }
    const int n0 = bn + tx*4;
    #pragma unroll
    for (int i = 0; i < 8; i++) {
        int m = bm + ty*8 + i;
        float2 f0 = *(float2*)&acc[i][0];
        float2 f1 = *(float2*)&acc[i][1];
        float4 o = make_float4(f0.x, f0.y, f1.x, f1.y);
        if (mode == 1) {
            const int tt = m & (NT-1);
            const float* xr = xin + (size_t)m*NC + n0;
            float4 xv4 = *(const float4*)xr;
            float4 xp4 = make_float4(0.f,0.f,0.f,0.f);
            if (tt != 0) xp4 = *(const float4*)(xr - NC);
            float4 t4 = *(const float4*)(tmf + n0);
            o.x = fmaf(xp4.x - xv4.x, t4.x + o.x, xv4.x);
            o.y = fmaf(xp4.y - xv4.y, t4.y + o.y, xv4.y);
            o.z = fmaf(xp4.z - xv4.z, t4.z + o.z, xv4.z);
            o.w = fmaf(xp4.w - xv4.w, t4.w + o.w, xv4.w);
        }
        *(float4*)(C + (size_t)m*NC + n0) = o;
    }
}

// ---------------- THIN GEMM: C = A(MxK) @ W(NxK)^T, N<=128, 32x32 tile ----------------
__global__ __launch_bounds__(256) void gemm_thin_kernel(
    const float* __restrict__ A, const float* __restrict__ W, float* __restrict__ C,
    int N, int K, int act)
{
    __shared__ float As[32][33];
    __shared__ __align__(16) float Ws[32][36];
    const int bm = blockIdx.x * 32;
    const int bn = blockIdx.y * 32;
    const int tid = threadIdx.x;
    const int lr = tid >> 3;
    const int lk = (tid & 7) * 4;
    const int ty = tid >> 3;
    const int tx = tid & 7;

    float acc0=0.f, acc1=0.f, acc2=0.f, acc3=0.f;
    const int wrow = bn + lr;

    for (int k0 = 0; k0 < K; k0 += 32) {
        float4 av = *(const float4*)(A + (size_t)(bm+lr)*K + k0 + lk);
        float4 wv = make_float4(0.f,0.f,0.f,0.f);
        if (wrow < N) wv = *(const float4*)(W + (size_t)wrow*K + k0 + lk);
        As[lk+0][lr]=av.x; As[lk+1][lr]=av.y; As[lk+2][lr]=av.z; As[lk+3][lr]=av.w;
        Ws[lk+0][lr]=wv.x; Ws[lk+1][lr]=wv.y; Ws[lk+2][lr]=wv.z; Ws[lk+3][lr]=wv.w;
        __syncthreads();
        #pragma unroll
        for (int kk = 0; kk < 32; kk++) {
            float a = As[kk][ty];
            float4 w4 = *(const float4*)&Ws[kk][tx*4];
            acc0 = fmaf(a, w4.x, acc0);
            acc1 = fmaf(a, w4.y, acc1);
            acc2 = fmaf(a, w4.z, acc2);
            acc3 = fmaf(a, w4.w, acc3);
        }
        __syncthreads();
    }
    if (act) { acc0=tanhf(acc0); acc1=tanhf(acc1); acc2=tanhf(acc2); acc3=tanhf(acc3); }
    const int m = bm + ty;
    const int n0 = bn + tx*4;
    float* cr = C + (size_t)m*N;
    if (n0   < N) cr[n0]   = acc0;
    if (n0+1 < N) cr[n0+1] = acc1;
    if (n0+2 < N) cr[n0+2] = acc2;
    if (n0+3 < N) cr[n0+3] = acc3;
}

// ---------------- token shift ----------------
__global__ __launch_bounds__(256) void shift_kernel(const float* __restrict__ x,
                                                    const float* __restrict__ tmx)
{
    const size_t i = (size_t)blockIdx.x*256 + threadIdx.x;
    const int c = (int)(i & (NC-1));
    const size_t tok = i >> 10;
    const int tt = (int)(tok & (NT-1));
    float xv = x[i];
    float xp = (tt == 0) ? 0.f : x[i - NC];
    g_xxx[i] = fmaf(xp - xv, tmx[c], xv);
}

// ---------------- post: all delta streams coalesced; ew/kf/kkn/bb ----------------
__global__ __launch_bounds__(256) void post_kernel(
    const float* __restrict__ td,  const float* __restrict__ ta5,
    const float* __restrict__ tma_, const float* __restrict__ tmk_)
{
    const int tok = blockIdx.x;
    const int tid = threadIdx.x;
    const size_t base = (size_t)tok*NC;
    const int c = tid * 4;
    float4 kraw = *(const float4*)(g_k   + base + c);
    float4 dw4  = *(const float4*)(g_dw  + base + c);
    float4 da4  = *(const float4*)(g_da  + base + c);
    float4 dma4 = *(const float4*)(g_dma + base + c);
    float4 dkk4 = *(const float4*)(g_dkk + base + c);
    float4 dmk4 = *(const float4*)(g_dmk + base + c);
    float4 td4  = *(const float4*)(td   + c);
    float4 ta4  = *(const float4*)(ta5  + c);
    float4 tm4  = *(const float4*)(tma_ + c);
    float4 tk4  = *(const float4*)(tmk_ + c);

    float kr[4] = {kraw.x, kraw.y, kraw.z, kraw.w};
    float uw[4] = {td4.x+dw4.x, td4.y+dw4.y, td4.z+dw4.z, td4.w+dw4.w};
    float ua[4] = {ta4.x+da4.x, ta4.y+da4.y, ta4.z+da4.z, ta4.w+da4.w};
    float um[4] = {tm4.x+dma4.x, tm4.y+dma4.y, tm4.z+dma4.z, tm4.w+dma4.w};
    float uk[4] = {tk4.x+dmk4.x, tk4.y+dmk4.y, tk4.z+dmk4.z, tk4.w+dmk4.w};
    float kkq[4] = {kr[0]+dkk4.x, kr[1]+dkk4.y, kr[2]+dkk4.z, kr[3]+dkk4.w};

    float ewv[4], kfv[4], avv[4];
    float ss = 0.f;
    #pragma unroll
    for (int q = 0; q < 4; q++) {
        float spz = -uw[q];
        float sp = (spz > 15.f) ? spz : log1pf(expf(spz));
        float w = -sp - 0.5f;
        ewv[q] = expf(w);
        float a  = 1.f/(1.f + expf(-ua[q]));
        float ma = 1.f/(1.f + expf(-um[q]));
        float mk = 1.f/(1.f + expf(-uk[q]));
        avv[q] = a;
        kfv[q] = kr[q] * (ma + a*(1.f - ma)) * expf(w*mk);
        ss = fmaf(kkq[q], kkq[q], ss);
    }
    ss += __shfl_xor_sync(0xffffffffu, ss, 1);
    ss += __shfl_xor_sync(0xffffffffu, ss, 2);
    ss += __shfl_xor_sync(0xffffffffu, ss, 4);
    ss += __shfl_xor_sync(0xffffffffu, ss, 8);
    const float rinv = 1.f / fmaxf(sqrtf(ss), 1e-12f);
    float4 kkn4, bb4, ew4, kf4;
    kkn4.x = kkq[0]*rinv; kkn4.y = kkq[1]*rinv; kkn4.z = kkq[2]*rinv; kkn4.w = kkq[3]*rinv;
    bb4.x = -kkn4.x*avv[0]; bb4.y = -kkn4.y*avv[1]; bb4.z = -kkn4.z*avv[2]; bb4.w = -kkn4.w*avv[3];
    ew4.x = ewv[0]; ew4.y = ewv[1]; ew4.z = ewv[2]; ew4.w = ewv[3];
    kf4.x = kfv[0]; kf4.y = kfv[1]; kf4.z = kfv[2]; kf4.w = kfv[3];
    *(float4*)(g_kkn + base + c) = kkn4;
    *(float4*)(g_bb  + base + c) = bb4;
    *(float4*)(g_ew  + base + c) = ew4;
    *(float4*)(g_kf  + base + c) = kf4;
}

// ---------------- RWKV-7 scan: chunked, f32x2, row-split ----------------
#define LOAD_ARR(arr, G) { \
    const int i0 = tid, i1 = tid + 128; \
    pf[2*(arr)+0] = *(const float4*)((G) + gb + (size_t)(i0>>4)*NC + ((i0&15)<<2)); \
    pf[2*(arr)+1] = *(const float4*)((G) + gb + (size_t)(i1>>4)*NC + ((i1&15)<<2)); }
#define STORE_ARR(arr, dst) { \
    const int i0 = tid, i1 = tid + 128; \
    *(float4*)&cbuf[dst][arr][i0>>4][(i0&15)<<2] = pf[2*(arr)+0]; \
    *(float4*)&cbuf[dst][arr][i1>>4][(i1&15)<<2] = pf[2*(arr)+1]; }

__global__ __launch_bounds__(128) void scan_kernel()
{
    const int blk = blockIdx.x;
    const int bh  = blk >> 1;
    const int rh  = blk & 1;
    const int b   = bh >> 4;
    const int h   = bh & 15;
    const int tid = threadIdx.x;
    const int row = rh*32 + (tid >> 2);
    const int sub = tid & 3;
    const int coff = sub * 16;

    __shared__ __align__(16) float cbuf[2][6][CH][64];

    unsigned long long S[8];
    #pragma unroll
    for (int j = 0; j < 8; j++) S[j] = 0ull;

    const size_t base = ((size_t)b*NT)*NC + (size_t)h*NNh;

    {
        const size_t gb = base;
        float4 pf[12];
        LOAD_ARR(0, g_r);  LOAD_ARR(1, g_ew); LOAD_ARR(2, g_kf);
        LOAD_ARR(3, g_v);  LOAD_ARR(4, g_kkn); LOAD_ARR(5, g_bb);
        STORE_ARR(0, 0); STORE_ARR(1, 0); STORE_ARR(2, 0);
        STORE_ARR(3, 0); STORE_ARR(4, 0); STORE_ARR(5, 0);
    }
    __syncthreads();

    for (int c = 0; c < NCH; c++) {
        const int buf = c & 1;
        const int nb  = buf ^ 1;
        float4 pf[12];
        if (c + 1 < NCH) {
            const size_t gb = base + (size_t)((c+1)*CH)*NC;
            LOAD_ARR(0, g_r);  LOAD_ARR(1, g_ew); LOAD_ARR(2, g_kf);
            LOAD_ARR(3, g_v);  LOAD_ARR(4, g_kkn); LOAD_ARR(5, g_bb);
        }
        const size_t ybase = base + (size_t)(c*CH)*NC + row;
        #pragma unroll 4
        for (int s = 0; s < CH; s++) {
            const ulonglong2* rp  = (const ulonglong2*)&cbuf[buf][0][s][coff];
            const ulonglong2* ewp = (const ulonglong2*)&cbuf[buf][1][s][coff];
            const ulonglong2* kfp = (const ulonglong2*)&cbuf[buf][2][s][coff];
            const ulonglong2* kkp = (const ulonglong2*)&cbuf[buf][4][s][coff];
            const ulonglong2* bbp = (const ulonglong2*)&cbuf[buf][5][s][coff];
            const float vv = cbuf[buf][3][s][row];
            unsigned long long a0 = 0ull, a1 = 0ull;
            #pragma unroll
            for (int j = 0; j < 4; j++) {
                ulonglong2 kq = kkp[j];
                fma2(a0, S[2*j+0], kq.x);
                fma2(a1, S[2*j+1], kq.y);
            }
            float2 fa0 = up2(a0), fa1 = up2(a1);
            float sab = (fa0.x + fa0.y) + (fa1.x + fa1.y);
            sab += __shfl_xor_sync(0xffffffffu, sab, 1);
            sab += __shfl_xor_sync(0xffffffffu, sab, 2);
            const unsigned long long sab2 = pk2(sab, sab);
            const unsigned long long vv2  = pk2(vv, vv);
            unsigned long long y0 = 0ull, y1 = 0ull;
            #pragma unroll
            for (int j = 0; j < 4; j++) {
                ulonglong2 eq = ewp[j], bq = bbp[j], kq = kfp[j], rq = rp[j];
                unsigned long long t0 = mul2(S[2*j+0], eq.x);
                fma2(t0, sab2, bq.x);
                fma2(t0, vv2,  kq.x);
                S[2*j+0] = t0;
                fma2(y0, t0, rq.x);
                unsigned long long t1 = mul2(S[2*j+1], eq.y);
                fma2(t1, sab2, bq.y);
                fma2(t1, vv2,  kq.y);
                S[2*j+1] = t1;
                fma2(y1, t1, rq.y);
            }
            float2 fy0 = up2(y0), fy1 = up2(y1);
            float yv = (fy0.x + fy0.y) + (fy1.x + fy1.y);
            yv += __shfl_xor_sync(0xffffffffu, yv, 1);
            yv += __shfl_xor_sync(0xffffffffu, yv, 2);
            if (sub == 0) g_y[ybase + (size_t)s*NC] = yv;
        }
        if (c + 1 < NCH) {
            STORE_ARR(0, nb); STORE_ARR(1, nb); STORE_ARR(2, nb);
            STORE_ARR(3, nb); STORE_ARR(4, nb); STORE_ARR(5, nb);
        }
        __syncthreads();
    }
}

// ---------------- tail: GroupNorm + r.k bonus + gate ----------------
__global__ __launch_bounds__(256) void tail_kernel(
    const float* __restrict__ lnw, const float* __restrict__ lnb,
    const float* __restrict__ faaaa)
{
    const int tok = blockIdx.x;
    const int tid = threadIdx.x;
    const size_t base = (size_t)tok*NC;
    float yv[4], vv[4];
    float sy=0.f, syy=0.f, srk=0.f;
    #pragma unroll
    for (int q = 0; q < 4; q++) {
        const int c = tid*4 + q;
        float y = g_y[base+c];
        float r = g_r[base+c];
        float k = g_kf[base+c];
        vv[q] = g_v[base+c];
        yv[q] = y;
        sy += y;
        syy = fmaf(y, y, syy);
        srk = fmaf(r*k, faaaa[c], srk);
    }
    #pragma unroll
    for (int o = 1; o < 16; o <<= 1) {
        sy  += __shfl_xor_sync(0xffffffffu, sy,  o);
        syy += __shfl_xor_sync(0xffffffffu, syy, o);
        srk += __shfl_xor_sync(0xffffffffu, srk, o);
    }
    const float mu  = sy * (1.f/64.f);
    const float var = syy * (1.f/64.f) - mu*mu;
    const float inv = 1.f / sqrtf(var + 0.00064f);
    #pragma unroll
    for (int q = 0; q < 4; q++) {
        const int c = tid*4 + q;
        float yn = (yv[q] - mu) * inv * lnw[c] + lnb[c];
        g_z[base+c] = (yn + srk*vv[q]) * g_g[base+c];
    }
}

// ---------------- host ----------------
static inline void launch_big(const float* A, int lda, const float* W, int ldw,
                              float* C, int M, int K,
                              const float* xin = 0, const float* tmf = 0, int mode = 0)
{
    dim3 grid(NC/64, M/128);
    gemm_big_kernel<<<grid, 256>>>(A, lda, W, ldw, C, K, xin, tmf, mode);
}
static inline void launch_thin(const float* A, const float* W, float* C,
                               int M, int N, int K, int act)
{
    dim3 grid(M/32, (N + 31)/32);
    gemm_thin_kernel<<<grid, 256>>>(A, W, C, N, K, act);
}

extern "C" void kernel_launch(void* const* d_in, const int* in_sizes, int n_in,
                              void* d_out, int out_size)
{
    const float* x     = (const float*)d_in[0];
    const float* tmx   = (const float*)d_in[1];
    const float* tm    = (const float*)d_in[2];
    const float* maaw1 = (const float*)d_in[3];
    const float* maaw2 = (const float*)d_in[4];
    const float* td    = (const float*)d_in[5];
    const float* tdw1  = (const float*)d_in[6];
    const float* tdw2  = (const float*)d_in[7];
    const float* ta5   = (const float*)d_in[8];
    const float* taw1  = (const float*)d_in[9];
    const float* taw2  = (const float*)d_in[10];
    const float* tkw1  = (const float*)d_in[11];
    const float* tkw2  = (const float*)d_in[12];
    const float* gw1   = (const float*)d_in[13];
    const float* gw2   = (const float*)d_in[14];
    const float* tma_  = (const float*)d_in[15];
    const float* maw1  = (const float*)d_in[16];
    const float* maw2  = (const float*)d_in[17];
    const float* tmk_  = (const float*)d_in[18];
    const float* mkw1  = (const float*)d_in[19];
    const float* mkw2  = (const float*)d_in[20];
    const float* recw  = (const float*)d_in[21];
    const float* keyw  = (const float*)d_in[22];
    const float* valw  = (const float*)d_in[23];
    const float* outw  = (const float*)d_in[24];
    const float* lnw   = (const float*)d_in[25];
    const float* lnb   = (const float*)d_in[26];
    const float* faaaa = (const float*)d_in[27];
    float* out = (float*)d_out;

    float *p_xxx, *p_mixh, *p_xrg, *p_xwa, *p_xk, *p_xv;
    float *p_r, *p_k, *p_v, *p_w1t, *p_a1, *p_ma1, *p_kk1, *p_mk1, *p_g1, *p_g, *p_z;
    float *p_dw, *p_da, *p_dma, *p_dkk, *p_dmk;
    cudaGetSymbolAddress((void**)&p_xxx,  g_xxx);
    cudaGetSymbolAddress((void**)&p_mixh, g_mixh);
    cudaGetSymbolAddress((void**)&p_xrg,  g_xrg);
    cudaGetSymbolAddress((void**)&p_xwa,  g_xwa);
    cudaGetSymbolAddress((void**)&p_xk,   g_xk);
    cudaGetSymbolAddress((void**)&p_xv,   g_xv);
    cudaGetSymbolAddress((void**)&p_r,    g_r);
    cudaGetSymbolAddress((void**)&p_k,    g_k);
    cudaGetSymbolAddress((void**)&p_v,    g_v);
    cudaGetSymbolAddress((void**)&p_w1t,  g_w1t);
    cudaGetSymbolAddress((void**)&p_a1,   g_a1);
    cudaGetSymbolAddress((void**)&p_ma1,  g_ma1);
    cudaGetSymbolAddress((void**)&p_kk1,  g_kk1);
    cudaGetSymbolAddress((void**)&p_mk1,  g_mk1);
    cudaGetSymbolAddress((void**)&p_g1,   g_g1);
    cudaGetSymbolAddress((void**)&p_g,    g_g);
    cudaGetSymbolAddress((void**)&p_z,    g_z);
    cudaGetSymbolAddress((void**)&p_dw,   g_dw);
    cudaGetSymbolAddress((void**)&p_da,   g_da);
    cudaGetSymbolAddress((void**)&p_dma,  g_dma);
    cudaGetSymbolAddress((void**)&p_dkk,  g_dkk);
    cudaGetSymbolAddress((void**)&p_dmk,  g_dmk);

    // 1. token shift
    shift_kernel<<<(NBT*NC)/256, 256>>>(x, tmx);
    // 2. mix hidden = tanh(xxx @ maa_w1^T)
    launch_thin(p_xxx, maaw1, p_mixh, NBT, 128, NC, 1);
    // 3. 4-way mixing as GEMMs (K=32) with fused token-shift epilogue
    launch_big(p_mixh + 0*32, 128, maaw2 + (size_t)0*NC*32, 32, p_xrg, NBT, 32, x, tm + 0*NC, 1);
    launch_big(p_mixh + 1*32, 128, maaw2 + (size_t)1*NC*32, 32, p_xwa, NBT, 32, x, tm + 1*NC, 1);
    launch_big(p_mixh + 2*32, 128, maaw2 + (size_t)2*NC*32, 32, p_xk,  NBT, 32, x, tm + 2*NC, 1);
    launch_big(p_mixh + 3*32, 128, maaw2 + (size_t)3*NC*32, 32, p_xv,  NBT, 32, x, tm + 3*NC, 1);
    // 4. big projections
    launch_big(p_xrg, NC, recw, NC, p_r, NBT, NC);
    launch_big(p_xk,  NC, keyw, NC, p_k, NBT, NC);
    launch_big(p_xv,  NC, valw, NC, p_v, NBT, NC);
    // 5. LoRA hiddens (thin)
    launch_thin(p_xwa, tdw1, p_w1t, NBT, 64,  NC, 1);
    launch_thin(p_xwa, taw1, p_a1,  NBT, 16,  NC, 0);
    launch_thin(p_xwa, maw1, p_ma1, NBT, 16,  NC, 0);
    launch_thin(p_xk,  tkw1, p_kk1, NBT, 16,  NC, 1);
    launch_thin(p_xk,  mkw1, p_mk1, NBT, 16,  NC, 0);
    launch_thin(p_xrg, gw1,  p_g1,  NBT, 128, NC, 1);
    // 6. gate g = g1 @ gate_w2^T
    launch_big(p_g1, 128, gw2, 128, p_g, NBT, 128);
    // 7. LoRA second stages as GEMMs (coalesced)
    launch_big(p_w1t, 64, tdw2, 64, p_dw,  NBT, 64);
    launch_big(p_a1,  16, taw2, 16, p_da,  NBT, 16);
    launch_big(p_ma1, 16, maw2, 16, p_dma, NBT, 16);
    launch_big(p_kk1, 16, tkw2, 16, p_dkk, NBT, 16);
    launch_big(p_mk1, 16, mkw2, 16, p_dmk, NBT, 16);
    // 8. elementwise post (all coalesced)
    post_kernel<<<NBT, 256>>>(td, ta5, tma_, tmk_);
    // 9. RWKV-7 scan (chunked, row-split)
    scan_kernel<<<NB*NH*2, 128>>>();
    // 10. GroupNorm + bonus + gate
    tail_kernel<<<NBT, 256>>>(lnw, lnb, faaaa);
    // 11. output projection
    launch_big(p_z, NC, outw, NC, out, NBT, NC);

    (void)in_sizes; (void)n_in; (void)out_size; (void)tdw1;
}

// round 9
// speedup vs baseline: 3.1837x; 1.0496x over previous
#include <cuda_runtime.h>
#include <cstdint>
#include <math.h>

#define NB 2
#define NT 1024
#define NC 1024
#define NH 16
#define NNh 64
#define NBT (NB*NT)
#define CH 16
#define NCH (NT/CH)

// ---------------- scratch (device globals; no allocation allowed) ----------------
__device__ float g_xxx[NBT*NC];
__device__ float g_mixh[NBT*128];
__device__ float g_xrg[NBT*NC];
__device__ float g_xwa[NBT*NC];
__device__ float g_xk [NBT*NC];
__device__ float g_xv [NBT*NC];
__device__ float g_r  [NBT*NC];
__device__ float g_k  [NBT*NC];
__device__ float g_v  [NBT*NC];
__device__ float g_w1t[NBT*64];
__device__ float g_a1 [NBT*16];
__device__ float g_ma1[NBT*16];
__device__ float g_kk1[NBT*16];
__device__ float g_mk1[NBT*16];
__device__ float g_g1 [NBT*128];
__device__ float g_g  [NBT*NC];
__device__ float g_ew [NBT*NC];
__device__ float g_kf [NBT*NC];
__device__ float g_kkn[NBT*NC];
__device__ float g_bb [NBT*NC];
__device__ float g_y  [NBT*NC];
__device__ float g_z  [NBT*NC];
__device__ float g_dw [NBT*NC];
__device__ float g_da [NBT*NC];
__device__ float g_dma[NBT*NC];
__device__ float g_dkk[NBT*NC];
__device__ float g_dmk[NBT*NC];

// ---------------- packed f32x2 helpers ----------------
__device__ __forceinline__ unsigned long long pk2(float lo, float hi) {
    unsigned long long r;
    asm("mov.b64 %0, {%1, %2};" : "=l"(r) : "f"(lo), "f"(hi));
    return r;
}
__device__ __forceinline__ void fma2(unsigned long long& d, unsigned long long a, unsigned long long b) {
    asm("fma.rn.f32x2 %0, %1, %2, %0;" : "+l"(d) : "l"(a), "l"(b));
}
__device__ __forceinline__ unsigned long long mul2(unsigned long long a, unsigned long long b) {
    unsigned long long r;
    asm("mul.rn.f32x2 %0, %1, %2;" : "=l"(r) : "l"(a), "l"(b));
    return r;
}
__device__ __forceinline__ float2 up2(unsigned long long a) {
    float2 f;
    asm("mov.b64 {%0, %1}, %2;" : "=f"(f.x), "=f"(f.y) : "l"(a));
    return f;
}

// ---------------- BIG GEMM: C(Mx1024) = A(MxK,lda) @ W(1024xK,ldw)^T ----------------
// 128x64 tile, double-buffered smem, one barrier per K-tile.
// mode 0: C = acc ; mode 1: C = x + (xprev - x) * (tmf + acc)
__global__ __launch_bounds__(256, 2) void gemm_big_kernel(
    const float* __restrict__ A, int lda,
    const float* __restrict__ W, int ldw,
    float* __restrict__ C, int K,
    const float* __restrict__ xin, const float* __restrict__ tmf, int mode)
{
    __shared__ __align__(16) float As[2][16][132];
    __shared__ __align__(16) float Ws[2][16][68];
    const int bm = blockIdx.y * 128;
    const int bn = blockIdx.x * 64;
    const int tid = threadIdx.x;
    const int tx = tid & 15;
    const int ty = tid >> 4;
    const int lr = tid >> 1;
    const int lka = (tid & 1) * 8;
    const int wr = tid >> 2;
    const int wka = (tid & 3) * 4;

    const float* Aptr = A + (size_t)(bm + lr)*lda + lka;
    const float* Wptr = W + (size_t)(bn + wr)*ldw + wka;

    unsigned long long acc[8][2];
    #pragma unroll
    for (int i = 0; i < 8; i++) { acc[i][0] = 0ull; acc[i][1] = 0ull; }

    // prologue: load tile 0
    float4 a0 = *(const float4*)(Aptr);
    float4 a1 = *(const float4*)(Aptr + 4);
    float4 wv = *(const float4*)(Wptr);
    As[0][lka+0][lr]=a0.x; As[0][lka+1][lr]=a0.y; As[0][lka+2][lr]=a0.z; As[0][lka+3][lr]=a0.w;
    As[0][lka+4][lr]=a1.x; As[0][lka+5][lr]=a1.y; As[0][lka+6][lr]=a1.z; As[0][lka+7][lr]=a1.w;
    Ws[0][wka+0][wr]=wv.x; Ws[0][wka+1][wr]=wv.y; Ws[0][wka+2][wr]=wv.z; Ws[0][wka+3][wr]=wv.w;
    __syncthreads();

    const int NIT = K >> 4;
    for (int c = 0; c < NIT; c++) {
        const int cb = c & 1;
        if (c + 1 < NIT) {
            const int k0 = (c + 1) << 4;
            a0 = *(const float4*)(Aptr + k0);
            a1 = *(const float4*)(Aptr + k0 + 4);
            wv = *(const float4*)(Wptr + k0);
        }
        #pragma unroll
        for (int kk = 0; kk < 16; kk++) {
            float4 f0 = *(const float4*)&As[cb][kk][ty*8];
            float4 f1 = *(const float4*)&As[cb][kk][ty*8+4];
            ulonglong2 q = *(const ulonglong2*)&Ws[cb][kk][tx*4];
            float a8[8] = {f0.x,f0.y,f0.z,f0.w,f1.x,f1.y,f1.z,f1.w};
            #pragma unroll
            for (int i = 0; i < 8; i++) {
                unsigned long long ad = pk2(a8[i], a8[i]);
                fma2(acc[i][0], ad, q.x);
                fma2(acc[i][1], ad, q.y);
            }
        }
        if (c + 1 < NIT) {
            const int nb = cb ^ 1;
            As[nb][lka+0][lr]=a0.x; As[nb][lka+1][lr]=a0.y; As[nb][lka+2][lr]=a0.z; As[nb][lka+3][lr]=a0.w;
            As[nb][lka+4][lr]=a1.x; As[nb][lka+5][lr]=a1.y; As[nb][lka+6][lr]=a1.z; As[nb][lka+7][lr]=a1.w;
            Ws[nb][wka+0][wr]=wv.x; Ws[nb][wka+1][wr]=wv.y; Ws[nb][wka+2][wr]=wv.z; Ws[nb][wka+3][wr]=wv.w;
        }
        __syncthreads();
    }

    const int n0 = bn + tx*4;
    #pragma unroll
    for (int i = 0; i < 8; i++) {
        int m = bm + ty*8 + i;
        float2 f0 = *(float2*)&acc[i][0];
        float2 f1 = *(float2*)&acc[i][1];
        float4 o = make_float4(f0.x, f0.y, f1.x, f1.y);
        if (mode == 1) {
            const int tt = m & (NT-1);
            const float* xr = xin + (size_t)m*NC + n0;
            float4 xv4 = *(const float4*)xr;
            float4 xp4 = make_float4(0.f,0.f,0.f,0.f);
            if (tt != 0) xp4 = *(const float4*)(xr - NC);
            float4 t4 = *(const float4*)(tmf + n0);
            o.x = fmaf(xp4.x - xv4.x, t4.x + o.x, xv4.x);
            o.y = fmaf(xp4.y - xv4.y, t4.y + o.y, xv4.y);
            o.z = fmaf(xp4.z - xv4.z, t4.z + o.z, xv4.z);
            o.w = fmaf(xp4.w - xv4.w, t4.w + o.w, xv4.w);
        }
        *(float4*)(C + (size_t)m*NC + n0) = o;
    }
}

// ---------------- THIN GEMM: C = A(MxK) @ W(NxK)^T, N<=128, 32x32 tile ----------------
__global__ __launch_bounds__(256) void gemm_thin_kernel(
    const float* __restrict__ A, const float* __restrict__ W, float* __restrict__ C,
    int N, int K, int act)
{
    __shared__ float As[32][33];
    __shared__ __align__(16) float Ws[32][36];
    const int bm = blockIdx.x * 32;
    const int bn = blockIdx.y * 32;
    const int tid = threadIdx.x;
    const int lr = tid >> 3;
    const int lk = (tid & 7) * 4;
    const int ty = tid >> 3;
    const int tx = tid & 7;

    float acc0=0.f, acc1=0.f, acc2=0.f, acc3=0.f;
    const int wrow = bn + lr;

    for (int k0 = 0; k0 < K; k0 += 32) {
        float4 av = *(const float4*)(A + (size_t)(bm+lr)*K + k0 + lk);
        float4 wv = make_float4(0.f,0.f,0.f,0.f);
        if (wrow < N) wv = *(const float4*)(W + (size_t)wrow*K + k0 + lk);
        As[lk+0][lr]=av.x; As[lk+1][lr]=av.y; As[lk+2][lr]=av.z; As[lk+3][lr]=av.w;
        Ws[lk+0][lr]=wv.x; Ws[lk+1][lr]=wv.y; Ws[lk+2][lr]=wv.z; Ws[lk+3][lr]=wv.w;
        __syncthreads();
        #pragma unroll
        for (int kk = 0; kk < 32; kk++) {
            float a = As[kk][ty];
            float4 w4 = *(const float4*)&Ws[kk][tx*4];
            acc0 = fmaf(a, w4.x, acc0);
            acc1 = fmaf(a, w4.y, acc1);
            acc2 = fmaf(a, w4.z, acc2);
            acc3 = fmaf(a, w4.w, acc3);
        }
        __syncthreads();
    }
    if (act) { acc0=tanhf(acc0); acc1=tanhf(acc1); acc2=tanhf(acc2); acc3=tanhf(acc3); }
    const int m = bm + ty;
    const int n0 = bn + tx*4;
    float* cr = C + (size_t)m*N;
    if (n0   < N) cr[n0]   = acc0;
    if (n0+1 < N) cr[n0+1] = acc1;
    if (n0+2 < N) cr[n0+2] = acc2;
    if (n0+3 < N) cr[n0+3] = acc3;
}

// ---------------- token shift ----------------
__global__ __launch_bounds__(256) void shift_kernel(const float* __restrict__ x,
                                                    const float* __restrict__ tmx)
{
    const size_t i = (size_t)blockIdx.x*256 + threadIdx.x;
    const int c = (int)(i & (NC-1));
    const size_t tok = i >> 10;
    const int tt = (int)(tok & (NT-1));
    float xv = x[i];
    float xp = (tt == 0) ? 0.f : x[i - NC];
    g_xxx[i] = fmaf(xp - xv, tmx[c], xv);
}

// ---------------- post ----------------
__global__ __launch_bounds__(256) void post_kernel(
    const float* __restrict__ td,  const float* __restrict__ ta5,
    const float* __restrict__ tma_, const float* __restrict__ tmk_)
{
    const int tok = blockIdx.x;
    const int tid = threadIdx.x;
    const size_t base = (size_t)tok*NC;
    const int c = tid * 4;
    float4 kraw = *(const float4*)(g_k   + base + c);
    float4 dw4  = *(const float4*)(g_dw  + base + c);
    float4 da4  = *(const float4*)(g_da  + base + c);
    float4 dma4 = *(const float4*)(g_dma + base + c);
    float4 dkk4 = *(const float4*)(g_dkk + base + c);
    float4 dmk4 = *(const float4*)(g_dmk + base + c);
    float4 td4  = *(const float4*)(td   + c);
    float4 ta4  = *(const float4*)(ta5  + c);
    float4 tm4  = *(const float4*)(tma_ + c);
    float4 tk4  = *(const float4*)(tmk_ + c);

    float kr[4] = {kraw.x, kraw.y, kraw.z, kraw.w};
    float uw[4] = {td4.x+dw4.x, td4.y+dw4.y, td4.z+dw4.z, td4.w+dw4.w};
    float ua[4] = {ta4.x+da4.x, ta4.y+da4.y, ta4.z+da4.z, ta4.w+da4.w};
    float um[4] = {tm4.x+dma4.x, tm4.y+dma4.y, tm4.z+dma4.z, tm4.w+dma4.w};
    float uk[4] = {tk4.x+dmk4.x, tk4.y+dmk4.y, tk4.z+dmk4.z, tk4.w+dmk4.w};
    float kkq[4] = {kr[0]+dkk4.x, kr[1]+dkk4.y, kr[2]+dkk4.z, kr[3]+dkk4.w};

    float ewv[4], kfv[4], avv[4];
    float ss = 0.f;
    #pragma unroll
    for (int q = 0; q < 4; q++) {
        float spz = -uw[q];
        float sp = (spz > 15.f) ? spz : log1pf(expf(spz));
        float w = -sp - 0.5f;
        ewv[q] = expf(w);
        float a  = 1.f/(1.f + expf(-ua[q]));
        float ma = 1.f/(1.f + expf(-um[q]));
        float mk = 1.f/(1.f + expf(-uk[q]));
        avv[q] = a;
        kfv[q] = kr[q] * (ma + a*(1.f - ma)) * expf(w*mk);
        ss = fmaf(kkq[q], kkq[q], ss);
    }
    ss += __shfl_xor_sync(0xffffffffu, ss, 1);
    ss += __shfl_xor_sync(0xffffffffu, ss, 2);
    ss += __shfl_xor_sync(0xffffffffu, ss, 4);
    ss += __shfl_xor_sync(0xffffffffu, ss, 8);
    const float rinv = 1.f / fmaxf(sqrtf(ss), 1e-12f);
    float4 kkn4, bb4, ew4, kf4;
    kkn4.x = kkq[0]*rinv; kkn4.y = kkq[1]*rinv; kkn4.z = kkq[2]*rinv; kkn4.w = kkq[3]*rinv;
    bb4.x = -kkn4.x*avv[0]; bb4.y = -kkn4.y*avv[1]; bb4.z = -kkn4.z*avv[2]; bb4.w = -kkn4.w*avv[3];
    ew4.x = ewv[0]; ew4.y = ewv[1]; ew4.z = ewv[2]; ew4.w = ewv[3];
    kf4.x = kfv[0]; kf4.y = kfv[1]; kf4.z = kfv[2]; kf4.w = kfv[3];
    *(float4*)(g_kkn + base + c) = kkn4;
    *(float4*)(g_bb  + base + c) = bb4;
    *(float4*)(g_ew  + base + c) = ew4;
    *(float4*)(g_kf  + base + c) = kf4;
}

// ---------------- RWKV-7 scan ----------------
#define LOAD_ARR(arr, G) { \
    const int i0 = tid, i1 = tid + 128; \
    pf[2*(arr)+0] = *(const float4*)((G) + gb + (size_t)(i0>>4)*NC + ((i0&15)<<2)); \
    pf[2*(arr)+1] = *(const float4*)((G) + gb + (size_t)(i1>>4)*NC + ((i1&15)<<2)); }
#define STORE_ARR(arr, dst) { \
    const int i0 = tid, i1 = tid + 128; \
    *(float4*)&cbuf[dst][arr][i0>>4][(i0&15)<<2] = pf[2*(arr)+0]; \
    *(float4*)&cbuf[dst][arr][i1>>4][(i1&15)<<2] = pf[2*(arr)+1]; }

__global__ __launch_bounds__(128) void scan_kernel()
{
    const int blk = blockIdx.x;
    const int bh  = blk >> 1;
    const int rh  = blk & 1;
    const int b   = bh >> 4;
    const int h   = bh & 15;
    const int tid = threadIdx.x;
    const int row = rh*32 + (tid >> 2);
    const int sub = tid & 3;
    const int coff = sub * 16;

    __shared__ __align__(16) float cbuf[2][6][CH][64];

    unsigned long long S[8];
    #pragma unroll
    for (int j = 0; j < 8; j++) S[j] = 0ull;

    const size_t base = ((size_t)b*NT)*NC + (size_t)h*NNh;

    {
        const size_t gb = base;
        float4 pf[12];
        LOAD_ARR(0, g_r);  LOAD_ARR(1, g_ew); LOAD_ARR(2, g_kf);
        LOAD_ARR(3, g_v);  LOAD_ARR(4, g_kkn); LOAD_ARR(5, g_bb);
        STORE_ARR(0, 0); STORE_ARR(1, 0); STORE_ARR(2, 0);
        STORE_ARR(3, 0); STORE_ARR(4, 0); STORE_ARR(5, 0);
    }
    __syncthreads();

    for (int c = 0; c < NCH; c++) {
        const int buf = c & 1;
        const int nb  = buf ^ 1;
        float4 pf[12];
        if (c + 1 < NCH) {
            const size_t gb = base + (size_t)((c+1)*CH)*NC;
            LOAD_ARR(0, g_r);  LOAD_ARR(1, g_ew); LOAD_ARR(2, g_kf);
            LOAD_ARR(3, g_v);  LOAD_ARR(4, g_kkn); LOAD_ARR(5, g_bb);
        }
        const size_t ybase = base + (size_t)(c*CH)*NC + row;
        #pragma unroll 4
        for (int s = 0; s < CH; s++) {
            const ulonglong2* rp  = (const ulonglong2*)&cbuf[buf][0][s][coff];
            const ulonglong2* ewp = (const ulonglong2*)&cbuf[buf][1][s][coff];
            const ulonglong2* kfp = (const ulonglong2*)&cbuf[buf][2][s][coff];
            const ulonglong2* kkp = (const ulonglong2*)&cbuf[buf][4][s][coff];
            const ulonglong2* bbp = (const ulonglong2*)&cbuf[buf][5][s][coff];
            const float vv = cbuf[buf][3][s][row];
            unsigned long long a0 = 0ull, a1 = 0ull;
            #pragma unroll
            for (int j = 0; j < 4; j++) {
                ulonglong2 kq = kkp[j];
                fma2(a0, S[2*j+0], kq.x);
                fma2(a1, S[2*j+1], kq.y);
            }
            float2 fa0 = up2(a0), fa1 = up2(a1);
            float sab = (fa0.x + fa0.y) + (fa1.x + fa1.y);
            sab += __shfl_xor_sync(0xffffffffu, sab, 1);
            sab += __shfl_xor_sync(0xffffffffu, sab, 2);
            const unsigned long long sab2 = pk2(sab, sab);
            const unsigned long long vv2  = pk2(vv, vv);
            unsigned long long y0 = 0ull, y1 = 0ull;
            #pragma unroll
            for (int j = 0; j < 4; j++) {
                ulonglong2 eq = ewp[j], bq = bbp[j], kq = kfp[j], rq = rp[j];
                unsigned long long t0 = mul2(S[2*j+0], eq.x);
                fma2(t0, sab2, bq.x);
                fma2(t0, vv2,  kq.x);
                S[2*j+0] = t0;
                fma2(y0, t0, rq.x);
                unsigned long long t1 = mul2(S[2*j+1], eq.y);
                fma2(t1, sab2, bq.y);
                fma2(t1, vv2,  kq.y);
                S[2*j+1] = t1;
                fma2(y1, t1, rq.y);
            }
            float2 fy0 = up2(y0), fy1 = up2(y1);
            float yv = (fy0.x + fy0.y) + (fy1.x + fy1.y);
            yv += __shfl_xor_sync(0xffffffffu, yv, 1);
            yv += __shfl_xor_sync(0xffffffffu, yv, 2);
            if (sub == 0) g_y[ybase + (size_t)s*NC] = yv;
        }
        if (c + 1 < NCH) {
            STORE_ARR(0, nb); STORE_ARR(1, nb); STORE_ARR(2, nb);
            STORE_ARR(3, nb); STORE_ARR(4, nb); STORE_ARR(5, nb);
        }
        __syncthreads();
    }
}

// ---------------- tail ----------------
__global__ __launch_bounds__(256) void tail_kernel(
    const float* __restrict__ lnw, const float* __restrict__ lnb,
    const float* __restrict__ faaaa)
{
    const int tok = blockIdx.x;
    const int tid = threadIdx.x;
    const size_t base = (size_t)tok*NC;
    float yv[4], vv[4];
    float sy=0.f, syy=0.f, srk=0.f;
    #pragma unroll
    for (int q = 0; q < 4; q++) {
        const int c = tid*4 + q;
        float y = g_y[base+c];
        float r = g_r[base+c];
        float k = g_kf[base+c];
        vv[q] = g_v[base+c];
        yv[q] = y;
        sy += y;
        syy = fmaf(y, y, syy);
        srk = fmaf(r*k, faaaa[c], srk);
    }
    #pragma unroll
    for (int o = 1; o < 16; o <<= 1) {
        sy  += __shfl_xor_sync(0xffffffffu, sy,  o);
        syy += __shfl_xor_sync(0xffffffffu, syy, o);
        srk += __shfl_xor_sync(0xffffffffu, srk, o);
    }
    const float mu  = sy * (1.f/64.f);
    const float var = syy * (1.f/64.f) - mu*mu;
    const float inv = 1.f / sqrtf(var + 0.00064f);
    #pragma unroll
    for (int q = 0; q < 4; q++) {
        const int c = tid*4 + q;
        float yn = (yv[q] - mu) * inv * lnw[c] + lnb[c];
        g_z[base+c] = (yn + srk*vv[q]) * g_g[base+c];
    }
}

// ---------------- host ----------------
static inline void launch_big(const float* A, int lda, const float* W, int ldw,
                              float* C, int M, int K,
                              const float* xin = 0, const float* tmf = 0, int mode = 0)
{
    dim3 grid(NC/64, M/128);
    gemm_big_kernel<<<grid, 256>>>(A, lda, W, ldw, C, K, xin, tmf, mode);
}
static inline void launch_thin(const float* A, const float* W, float* C,
                               int M, int N, int K, int act)
{
    dim3 grid(M/32, (N + 31)/32);
    gemm_thin_kernel<<<grid, 256>>>(A, W, C, N, K, act);
}

extern "C" void kernel_launch(void* const* d_in, const int* in_sizes, int n_in,
                              void* d_out, int out_size)
{
    const float* x     = (const float*)d_in[0];
    const float* tmx   = (const float*)d_in[1];
    const float* tm    = (const float*)d_in[2];
    const float* maaw1 = (const float*)d_in[3];
    const float* maaw2 = (const float*)d_in[4];
    const float* td    = (const float*)d_in[5];
    const float* tdw1  = (const float*)d_in[6];
    const float* tdw2  = (const float*)d_in[7];
    const float* ta5   = (const float*)d_in[8];
    const float* taw1  = (const float*)d_in[9];
    const float* taw2  = (const float*)d_in[10];
    const float* tkw1  = (const float*)d_in[11];
    const float* tkw2  = (const float*)d_in[12];
    const float* gw1   = (const float*)d_in[13];
    const float* gw2   = (const float*)d_in[14];
    const float* tma_  = (const float*)d_in[15];
    const float* maw1  = (const float*)d_in[16];
    const float* maw2  = (const float*)d_in[17];
    const float* tmk_  = (const float*)d_in[18];
    const float* mkw1  = (const float*)d_in[19];
    const float* mkw2  = (const float*)d_in[20];
    const float* recw  = (const float*)d_in[21];
    const float* keyw  = (const float*)d_in[22];
    const float* valw  = (const float*)d_in[23];
    const float* outw  = (const float*)d_in[24];
    const float* lnw   = (const float*)d_in[25];
    const float* lnb   = (const float*)d_in[26];
    const float* faaaa = (const float*)d_in[27];
    float* out = (float*)d_out;

    float *p_xxx, *p_mixh, *p_xrg, *p_xwa, *p_xk, *p_xv;
    float *p_r, *p_k, *p_v, *p_w1t, *p_a1, *p_ma1, *p_kk1, *p_mk1, *p_g1, *p_g, *p_z;
    float *p_dw, *p_da, *p_dma, *p_dkk, *p_dmk;
    cudaGetSymbolAddress((void**)&p_xxx,  g_xxx);
    cudaGetSymbolAddress((void**)&p_mixh, g_mixh);
    cudaGetSymbolAddress((void**)&p_xrg,  g_xrg);
    cudaGetSymbolAddress((void**)&p_xwa,  g_xwa);
    cudaGetSymbolAddress((void**)&p_xk,   g_xk);
    cudaGetSymbolAddress((void**)&p_xv,   g_xv);
    cudaGetSymbolAddress((void**)&p_r,    g_r);
    cudaGetSymbolAddress((void**)&p_k,    g_k);
    cudaGetSymbolAddress((void**)&p_v,    g_v);
    cudaGetSymbolAddress((void**)&p_w1t,  g_w1t);
    cudaGetSymbolAddress((void**)&p_a1,   g_a1);
    cudaGetSymbolAddress((void**)&p_ma1,  g_ma1);
    cudaGetSymbolAddress((void**)&p_kk1,  g_kk1);
    cudaGetSymbolAddress((void**)&p_mk1,  g_mk1);
    cudaGetSymbolAddress((void**)&p_g1,   g_g1);
    cudaGetSymbolAddress((void**)&p_g,    g_g);
    cudaGetSymbolAddress((void**)&p_z,    g_z);
    cudaGetSymbolAddress((void**)&p_dw,   g_dw);
    cudaGetSymbolAddress((void**)&p_da,   g_da);
    cudaGetSymbolAddress((void**)&p_dma,  g_dma);
    cudaGetSymbolAddress((void**)&p_dkk,  g_dkk);
    cudaGetSymbolAddress((void**)&p_dmk,  g_dmk);

    // 1. token shift
    shift_kernel<<<(NBT*NC)/256, 256>>>(x, tmx);
    // 2. mix hidden = tanh(xxx @ maa_w1^T)
    launch_thin(p_xxx, maaw1, p_mixh, NBT, 128, NC, 1);
    // 3. 4-way mixing as GEMMs (K=32) with fused token-shift epilogue
    launch_big(p_mixh + 0*32, 128, maaw2 + (size_t)0*NC*32, 32, p_xrg, NBT, 32, x, tm + 0*NC, 1);
    launch_big(p_mixh + 1*32, 128, maaw2 + (size_t)1*NC*32, 32, p_xwa, NBT, 32, x, tm + 1*NC, 1);
    launch_big(p_mixh + 2*32, 128, maaw2 + (size_t)2*NC*32, 32, p_xk,  NBT, 32, x, tm + 2*NC, 1);
    launch_big(p_mixh + 3*32, 128, maaw2 + (size_t)3*NC*32, 32, p_xv,  NBT, 32, x, tm + 3*NC, 1);
    // 4. big projections
    launch_big(p_xrg, NC, recw, NC, p_r, NBT, NC);
    launch_big(p_xk,  NC, keyw, NC, p_k, NBT, NC);
    launch_big(p_xv,  NC, valw, NC, p_v, NBT, NC);
    // 5. LoRA hiddens (thin)
    launch_thin(p_xwa, tdw1, p_w1t, NBT, 64,  NC, 1);
    launch_thin(p_xwa, taw1, p_a1,  NBT, 16,  NC, 0);
    launch_thin(p_xwa, maw1, p_ma1, NBT, 16,  NC, 0);
    launch_thin(p_xk,  tkw1, p_kk1, NBT, 16,  NC, 1);
    launch_thin(p_xk,  mkw1, p_mk1, NBT, 16,  NC, 0);
    launch_thin(p_xrg, gw1,  p_g1,  NBT, 128, NC, 1);
    // 6. gate g = g1 @ gate_w2^T
    launch_big(p_g1, 128, gw2, 128, p_g, NBT, 128);
    // 7. LoRA second stages as GEMMs
    launch_big(p_w1t, 64, tdw2, 64, p_dw,  NBT, 64);
    launch_big(p_a1,  16, taw2, 16, p_da,  NBT, 16);
    launch_big(p_ma1, 16, maw2, 16, p_dma, NBT, 16);
    launch_big(p_kk1, 16, tkw2, 16, p_dkk, NBT, 16);
    launch_big(p_mk1, 16, mkw2, 16, p_dmk, NBT, 16);
    // 8. elementwise post
    post_kernel<<<NBT, 256>>>(td, ta5, tma_, tmk_);
    // 9. RWKV-7 scan
    scan_kernel<<<NB*NH*2, 128>>>();
    // 10. GroupNorm + bonus + gate
    tail_kernel<<<NBT, 256>>>(lnw, lnb, faaaa);
    // 11. output projection
    launch_big(p_z, NC, outw, NC, out, NBT, NC);

    (void)in_sizes; (void)n_in; (void)out_size; (void)tdw1;
}